// round 13
// baseline (speedup 1.0000x reference)
#include <cuda_runtime.h>
#include <cuda_bf16.h>
#include <math.h>
#include <stdint.h>

// Problem constants
#define BB 1
#define HH 64
#define WW 64
#define CC 256
#define HEADS 8
#define HD 32
#define KK 7
#define DIL 2
#define FF 1024
#define NTOK (HH*WW)            // 4096
#define SCALE 0.17677669529663687f  // 1/sqrt(32)

// ---------------- scratch (device globals; no runtime alloc) ----------------
__device__ __nv_bfloat16 g_hs [NTOK*CC];     // LN1(x), bf16 (GEMM A)
__device__ float         g_q  [NTOK*CC];     // q fp32, pre-scaled
__device__ __nv_bfloat16 g_k  [NTOK*CC];     // k bf16
__device__ __nv_bfloat16 g_v  [NTOK*CC];     // v bf16
__device__ __nv_bfloat16 g_ctx[NTOK*CC];     // attention context, bf16
__device__ float         g_hs2[NTOK*CC];     // x + attn_out, fp32
__device__ __nv_bfloat16 g_y  [NTOK*CC];     // LN2(hs2), bf16
__device__ __nv_bfloat16 g_t  [NTOK*FF];     // gelu(y@w1+b1), bf16
// bf16 weights, plain [k][n] layout
__device__ __nv_bfloat16 g_wqkv_b[256*768];
__device__ __nv_bfloat16 g_wo_b  [256*256];
__device__ __nv_bfloat16 g_w1_b  [256*1024];
__device__ __nv_bfloat16 g_w2_b  [1024*256];
__device__ float         g_bqkv  [768];

__device__ __forceinline__ float4 ld4(const float* p) {
    return *reinterpret_cast<const float4*>(p);
}
__device__ __forceinline__ float2 bf2f(uint32_t u) {
    __nv_bfloat162 h = *reinterpret_cast<__nv_bfloat162*>(&u);
    return __bfloat1622float2(h);
}
__device__ __forceinline__ float2 ffma2(float2 a, float2 b, float2 c) {
    float2 d;
    asm("fma.rn.f32x2 %0, %1, %2, %3;"
        : "=l"(*reinterpret_cast<uint64_t*>(&d))
        : "l"(*reinterpret_cast<const uint64_t*>(&a)),
          "l"(*reinterpret_cast<const uint64_t*>(&b)),
          "l"(*reinterpret_cast<const uint64_t*>(&c)));
    return d;
}
__device__ __forceinline__ float2 fmul2(float2 a, float2 b) {
    float2 d;
    asm("mul.rn.f32x2 %0, %1, %2;"
        : "=l"(*reinterpret_cast<uint64_t*>(&d))
        : "l"(*reinterpret_cast<const uint64_t*>(&a)),
          "l"(*reinterpret_cast<const uint64_t*>(&b)));
    return d;
}
__device__ __forceinline__ uint32_t smem_u32(const void* p) {
    uint32_t a;
    asm("{ .reg .u64 t; cvta.to.shared.u64 t, %1; cvt.u32.u64 %0, t; }"
        : "=r"(a) : "l"(p));
    return a;
}
__device__ __forceinline__ void ldsm_x4(uint32_t (&r)[4], uint32_t addr) {
    asm volatile("ldmatrix.sync.aligned.m8n8.x4.shared.b16 {%0,%1,%2,%3}, [%4];"
        : "=r"(r[0]), "=r"(r[1]), "=r"(r[2]), "=r"(r[3]) : "r"(addr));
}
__device__ __forceinline__ void ldsm_x4_t(uint32_t (&r)[4], uint32_t addr) {
    asm volatile("ldmatrix.sync.aligned.m8n8.x4.trans.shared.b16 {%0,%1,%2,%3}, [%4];"
        : "=r"(r[0]), "=r"(r[1]), "=r"(r[2]), "=r"(r[3]) : "r"(addr));
}
__device__ __forceinline__ void mma_bf16(float (&d)[4], const uint32_t (&a)[4],
                                         const uint32_t (&b)[2]) {
    asm volatile(
        "mma.sync.aligned.m16n8k16.row.col.f32.bf16.bf16.f32 "
        "{%0,%1,%2,%3}, {%4,%5,%6,%7}, {%8,%9}, {%0,%1,%2,%3};\n"
        : "+f"(d[0]), "+f"(d[1]), "+f"(d[2]), "+f"(d[3])
        : "r"(a[0]), "r"(a[1]), "r"(a[2]), "r"(a[3]),
          "r"(b[0]), "r"(b[1]));
}
__device__ __forceinline__ void cpa16(uint32_t dst, const void* src) {
    asm volatile("cp.async.cg.shared.global [%0], [%1], 16;"
        :: "r"(dst), "l"(src) : "memory");
}
#define CP_COMMIT() asm volatile("cp.async.commit_group;" ::: "memory")
#define CP_WAIT(n)  asm volatile("cp.async.wait_group %0;" :: "n"(n) : "memory")

// ---------------- weight pack: fp32 -> bf16 plain [k][n], vectorized --------
__device__ __forceinline__ uint2 f4_to_bf4(float4 v) {
    __nv_bfloat162 h0 = __floats2bfloat162_rn(v.x, v.y);
    __nv_bfloat162 h1 = __floats2bfloat162_rn(v.z, v.w);
    return make_uint2(*reinterpret_cast<uint32_t*>(&h0),
                      *reinterpret_cast<uint32_t*>(&h1));
}

__global__ void pack_kernel(const float* __restrict__ wq, const float* __restrict__ wk,
                            const float* __restrict__ wv, const float* __restrict__ wo,
                            const float* __restrict__ w1, const float* __restrict__ w2,
                            const float* __restrict__ bq, const float* __restrict__ bk,
                            const float* __restrict__ bv)
{
    int i4 = blockIdx.x * 256 + threadIdx.x;     // vector (4-elem) index
    if (i4 < 49152) {                            // wqkv: 256x768
        int idx = i4 * 4;
        int k = idx / 768, n = idx % 768;
        const float* W; int nn;
        if      (n < 256) { W = wq; nn = n; }
        else if (n < 512) { W = wk; nn = n - 256; }
        else              { W = wv; nn = n - 512; }
        float4 v = ld4(W + (size_t)k * 256 + nn);
        *reinterpret_cast<uint2*>(g_wqkv_b + idx) = f4_to_bf4(v);
    } else if (i4 < 65536) {                     // wo
        int t = (i4 - 49152) * 4;
        *reinterpret_cast<uint2*>(g_wo_b + t) = f4_to_bf4(ld4(wo + t));
    } else if (i4 < 131072) {                    // w1
        int t = (i4 - 65536) * 4;
        *reinterpret_cast<uint2*>(g_w1_b + t) = f4_to_bf4(ld4(w1 + t));
    } else if (i4 < 196608) {                    // w2
        int t = (i4 - 131072) * 4;
        *reinterpret_cast<uint2*>(g_w2_b + t) = f4_to_bf4(ld4(w2 + t));
    }
    if (i4 < 768) {
        float v;
        if      (i4 < 256) v = bq[i4];
        else if (i4 < 512) v = bk[i4 - 256];
        else               v = bv[i4 - 512];
        g_bqkv[i4] = v;
    }
}

// ---------------- LayerNorm: one warp per row, 8 rows/block ----------------
__global__ void ln_kernel(const float* __restrict__ x, const float* __restrict__ g,
                          const float* __restrict__ b, __nv_bfloat16* __restrict__ out)
{
    const int row  = blockIdx.x * 8 + (threadIdx.x >> 5);
    const int lane = threadIdx.x & 31;
    const float* xr = x + (size_t)row * CC + lane * 8;
    float4 v0 = ld4(xr), v1 = ld4(xr + 4);
    float s  = v0.x + v0.y + v0.z + v0.w + v1.x + v1.y + v1.z + v1.w;
    float sq = v0.x*v0.x + v0.y*v0.y + v0.z*v0.z + v0.w*v0.w
             + v1.x*v1.x + v1.y*v1.y + v1.z*v1.z + v1.w*v1.w;
    #pragma unroll
    for (int o = 16; o; o >>= 1) {
        s  += __shfl_xor_sync(0xffffffffu, s,  o);
        sq += __shfl_xor_sync(0xffffffffu, sq, o);
    }
    float mean = s * (1.0f/CC);
    float var  = sq * (1.0f/CC) - mean*mean;
    float inv  = rsqrtf(var + 1e-5f);
    float4 g0 = ld4(g + lane*8), g1 = ld4(g + lane*8 + 4);
    float4 b0 = ld4(b + lane*8), b1 = ld4(b + lane*8 + 4);
    __nv_bfloat162 o0 = __floats2bfloat162_rn((v0.x-mean)*inv*g0.x + b0.x,
                                              (v0.y-mean)*inv*g0.y + b0.y);
    __nv_bfloat162 o1 = __floats2bfloat162_rn((v0.z-mean)*inv*g0.z + b0.z,
                                              (v0.w-mean)*inv*g0.w + b0.w);
    __nv_bfloat162 o2 = __floats2bfloat162_rn((v1.x-mean)*inv*g1.x + b1.x,
                                              (v1.y-mean)*inv*g1.y + b1.y);
    __nv_bfloat162 o3 = __floats2bfloat162_rn((v1.z-mean)*inv*g1.z + b1.z,
                                              (v1.w-mean)*inv*g1.w + b1.w);
    uint4 pk = make_uint4(*reinterpret_cast<uint32_t*>(&o0),
                          *reinterpret_cast<uint32_t*>(&o1),
                          *reinterpret_cast<uint32_t*>(&o2),
                          *reinterpret_cast<uint32_t*>(&o3));
    *reinterpret_cast<uint4*>(out + (size_t)row * CC + lane * 8) = pk;
}

// ---------------- bf16 tensor-core GEMM: cp.async 4-stage pipeline ----------
// BM64 tiles: 2Mx4N warps, warp 32x16 (2x2 frags), minctas=3.
// EPI 1: gelu(+bias) ; EPI 2: +bias + res ; EPI 3: qkv split
#define A_STR 20   // uint32 per A row (80B)
#define B_STR 36   // uint32 per B row (144B)
#define NSTG 4
#define BMT 64

__device__ __forceinline__ void store2(float* p, float v0, float v1) {
    *reinterpret_cast<float2*>(p) = make_float2(v0, v1);
}
__device__ __forceinline__ void store2(__nv_bfloat16* p, float v0, float v1) {
    *reinterpret_cast<__nv_bfloat162*>(p) = __floats2bfloat162_rn(v0, v1);
}

template<int EPI, typename OutT>
__global__ void __launch_bounds__(256, 3)
bgemm_kernel(const __nv_bfloat16* __restrict__ A, const __nv_bfloat16* __restrict__ W,
             const float* __restrict__ bias, const float* __restrict__ res,
             OutT* __restrict__ C, __nv_bfloat16* __restrict__ kout,
             __nv_bfloat16* __restrict__ vout, int M, int N, int K)
{
    constexpr int WM = 2, WN = 4, NF = 2;
    constexpr uint32_t A_STG = BMT * A_STR * 4;
    constexpr uint32_t B_STG = 32 * B_STR * 4;

    __shared__ __align__(16) uint32_t As[NSTG][BMT * A_STR];
    __shared__ __align__(16) uint32_t Bs[NSTG][32 * B_STR];

    const int tid  = threadIdx.x;
    const int lane = tid & 31, warp = tid >> 5;
    const int wm = warp % WM, wn = warp / WM;
    const int g = lane >> 2, c = lane & 3;
    const int bm = blockIdx.y * BMT, bn = blockIdx.x * 64;

    const int arow = (tid >> 1) & 63, ahalf = (tid & 1);
    const bool aload = (tid < 128);
    const int bkrow = tid >> 3, bnch = (tid & 7) * 8;
    const __nv_bfloat16* Ag = A + (size_t)(bm + arow) * K + ahalf * 16;
    const __nv_bfloat16* Wg = W + (size_t)bkrow * N + bn + bnch;

    const uint32_t aBase = smem_u32(As);
    const uint32_t bBase = smem_u32(Bs);
    const uint32_t asto = (uint32_t)(arow * A_STR + ahalf * 8) * 4;
    const uint32_t bsto = (uint32_t)(bkrow * B_STR + (tid & 7) * 4) * 4;

    const uint32_t aoff = (uint32_t)(wm*32 + (lane & 15)) * 80 + (lane >> 4) * 16;
    const uint32_t boff = (uint32_t)(lane & 15) * 144 +
                          (uint32_t)(wn*(NF*8) + (lane >> 4)*8) * 2;

    float acc[2][NF][4];
    #pragma unroll
    for (int mf = 0; mf < 2; mf++)
        #pragma unroll
        for (int nf = 0; nf < NF; nf++)
            #pragma unroll
            for (int e = 0; e < 4; e++) acc[mf][nf][e] = 0.f;

    const int NT = K / 32;

    auto issue = [&](int kt, int s) {
        if (aload) {
            const __nv_bfloat16* ag = Ag + kt * 32;
            uint32_t d = aBase + (uint32_t)s * A_STG + asto;
            cpa16(d, ag);
            cpa16(d + 16, ag + 8);
        }
        cpa16(bBase + (uint32_t)s * B_STG + bsto, Wg + (size_t)kt * 32 * N);
        CP_COMMIT();
    };

    // prologue: NSTG-1 stages in flight
    #pragma unroll
    for (int p = 0; p < NSTG - 1; p++) issue(p, p);

    for (int kt = 0; kt < NT; kt++) {
        CP_WAIT(NSTG - 2);
        __syncthreads();
        const int s = kt % NSTG;
        if (kt + NSTG - 1 < NT) {
            issue(kt + NSTG - 1, (kt + NSTG - 1) % NSTG);
        } else {
            CP_COMMIT();   // empty group keeps wait_group invariant at the tail
        }

        const uint32_t ab = aBase + (uint32_t)s * A_STG;
        const uint32_t bb = bBase + (uint32_t)s * B_STG;
        #pragma unroll
        for (int ks = 0; ks < 32; ks += 16) {
            uint32_t af[2][4], bf[NF][2];
            #pragma unroll
            for (int mf = 0; mf < 2; mf++)
                ldsm_x4(af[mf], ab + aoff + (uint32_t)(mf * 16 * 80 + ks * 2));
            {
                uint32_t br[4];
                ldsm_x4_t(br, bb + boff + (uint32_t)(ks * 144));
                bf[0][0] = br[0]; bf[0][1] = br[1];
                bf[1][0] = br[2]; bf[1][1] = br[3];
            }
            #pragma unroll
            for (int mf = 0; mf < 2; mf++)
                #pragma unroll
                for (int nf = 0; nf < NF; nf++)
                    mma_bf16(acc[mf][nf], af[mf], bf[nf]);
        }
    }
    __syncthreads();

    #pragma unroll
    for (int mf = 0; mf < 2; mf++) {
        #pragma unroll
        for (int nf = 0; nf < NF; nf++) {
            int row0 = bm + wm * 32 + mf * 16 + g;
            int col  = bn + wn * (NF*8) + nf * 8 + c * 2;
            float bx = bias[col], by = bias[col + 1];
            #pragma unroll
            for (int h = 0; h < 2; h++) {
                int row = row0 + h * 8;
                float v0 = acc[mf][nf][h * 2 + 0] + bx;
                float v1 = acc[mf][nf][h * 2 + 1] + by;
                if (EPI == 1) {
                    v0 *= normcdff(v0);
                    v1 *= normcdff(v1);
                } else if (EPI == 2) {
                    float2 r = *reinterpret_cast<const float2*>(res + (size_t)row * N + col);
                    v0 += r.x; v1 += r.y;
                }
                if (EPI == 3) {
                    if (col < 256) {
                        store2((float*)C + (size_t)row * 256 + col, v0 * SCALE, v1 * SCALE);
                    } else if (col < 512) {
                        store2(kout + (size_t)row * 256 + (col - 256), v0, v1);
                    } else {
                        store2(vout + (size_t)row * 256 + (col - 512), v0, v1);
                    }
                } else {
                    store2(C + (size_t)row * N + col, v0, v1);
                }
            }
        }
    }
}

// ---------------- dilated neighborhood attention: quad-token sharing --------
// Register-dieted: score and PV phases each run as TWO sequential query-pair
// passes (unroll 1) so qv/acc live ranges are halved; launch_bounds(256,3).
__global__ void __launch_bounds__(256, 3)
attn_kernel(const float* __restrict__ q, const __nv_bfloat16* __restrict__ k,
            const __nv_bfloat16* __restrict__ v, const float* __restrict__ rpb,
            __nv_bfloat16* __restrict__ ctx)
{
    __shared__ float sc[HEADS][4][64];

    const int head = threadIdx.y;
    const int lane = threadIdx.x;
    const int gg = lane >> 2, e = lane & 3;

    const int b   = blockIdx.x;
    const int bi  = b & 15, bj = (b >> 4) & 15, par = b >> 8;
    const int ri  = par & 1, rj = par >> 1;
    const int gi0 = bi * 2, gj0 = bj * 2;

    int si0 = gi0 - 3; si0 = si0 < 0 ? 0 : (si0 > 25 ? 25 : si0);
    int si1 = gi0 - 2; si1 = si1 < 0 ? 0 : (si1 > 25 ? 25 : si1);
    int sj0 = gj0 - 3; sj0 = sj0 < 0 ? 0 : (sj0 > 25 ? 25 : sj0);
    int sj1 = gj0 - 2; sj1 = sj1 < 0 ? 0 : (sj1 > 25 ? 25 : sj1);
    const int dr1 = si1 - si0, dc1 = sj1 - sj0;

    int sjg = sj0 + gg; sjg = sjg > 31 ? 31 : sjg;
    const int kj = sjg * 2 + rj;
    const int choff = head * HD + e * 8;
    const int kcoff = kj * CC + choff;

    // ---- score phase: two query-pair passes (row a = pass index) ----
    #pragma unroll 1
    for (int a = 0; a < 2; a++) {
        float2 qv[2][4];
        #pragma unroll
        for (int c = 0; c < 2; c++) {
            int tok = (2*(gi0 + a) + ri) * WW + 2*(gj0 + c) + rj;
            const float* qp = q + (size_t)tok * CC + choff;
            float4 qa = ld4(qp), qb = ld4(qp + 4);
            qv[c][0] = make_float2(qa.x, qa.y);
            qv[c][1] = make_float2(qa.z, qa.w);
            qv[c][2] = make_float2(qb.x, qb.y);
            qv[c][3] = make_float2(qb.z, qb.w);
        }
        #pragma unroll
        for (int t = 0; t < 8; t++) {
            int sit = si0 + t; sit = sit > 31 ? 31 : sit;
            const int ki = sit * 2 + ri;
            uint4 u = *reinterpret_cast<const uint4*>(k + ki * (WW*CC) + kcoff);
            float2 k0 = bf2f(u.x), k1 = bf2f(u.y), k2 = bf2f(u.z), k3 = bf2f(u.w);
            #pragma unroll
            for (int c = 0; c < 2; c++) {
                float2 p2 = fmul2(qv[c][0], k0);
                p2 = ffma2(qv[c][1], k1, p2);
                p2 = ffma2(qv[c][2], k2, p2);
                p2 = ffma2(qv[c][3], k3, p2);
                float pt = p2.x + p2.y;
                pt += __shfl_xor_sync(0xffffffffu, pt, 1);
                pt += __shfl_xor_sync(0xffffffffu, pt, 2);
                if (e == 0) sc[head][a*2 + c][t*8 + gg] = pt;
            }
        }
    }
    __syncwarp();

    // ---- softmax per query: bias + mask + normalize ----
    const float* br = rpb + head * 169;
    float inv[4];
    #pragma unroll
    for (int qq_ = 0; qq_ < 4; qq_++) {
        const int a = qq_ >> 1, c = qq_ & 1;
        const int dra = a ? dr1 : 0, dcc = c ? dc1 : 0;
        const int Bq = (si0 - gi0 - a + 6) * 13 + (sj0 - gj0 - c + 6);
        float s1, s2;
        {
            int p = lane, pr = p >> 3, pc = p & 7;
            bool val = (pr >= dra) && (pr < dra + 7) && (pc >= dcc) && (pc < dcc + 7);
            s1 = val ? sc[head][qq_][p] + br[Bq + pr*13 + pc] : -1e30f;
        }
        {
            int p = lane + 32, pr = p >> 3, pc = p & 7;
            bool val = (pr >= dra) && (pr < dra + 7) && (pc >= dcc) && (pc < dcc + 7);
            s2 = val ? sc[head][qq_][p] + br[Bq + pr*13 + pc] : -1e30f;
        }
        float m = fmaxf(s1, s2);
        #pragma unroll
        for (int o = 16; o; o >>= 1) m = fmaxf(m, __shfl_xor_sync(0xffffffffu, m, o));
        float e1 = __expf(s1 - m), e2 = __expf(s2 - m);
        float ss = e1 + e2;
        #pragma unroll
        for (int o = 16; o; o >>= 1) ss += __shfl_xor_sync(0xffffffffu, ss, o);
        sc[head][qq_][lane]      = e1;
        sc[head][qq_][lane + 32] = e2;
        inv[qq_] = 1.0f / ss;
    }
    __syncwarp();

    // ---- PV phase: two query-pair passes ----
    #pragma unroll 1
    for (int a = 0; a < 2; a++) {
        float2 acc[2][4];
        #pragma unroll
        for (int c = 0; c < 2; c++)
            #pragma unroll
            for (int i = 0; i < 4; i++) acc[c][i] = make_float2(0.f, 0.f);

        #pragma unroll
        for (int t = 0; t < 8; t++) {
            int sit = si0 + t; sit = sit > 31 ? 31 : sit;
            const int ki = sit * 2 + ri;
            uint4 u = *reinterpret_cast<const uint4*>(v + ki * (WW*CC) + kcoff);
            float2 v0 = bf2f(u.x), v1 = bf2f(u.y), v2 = bf2f(u.z), v3 = bf2f(u.w);
            #pragma unroll
            for (int c = 0; c < 2; c++) {
                float w = sc[head][a*2 + c][t*8 + gg];
                float2 w2 = make_float2(w, w);
                acc[c][0] = ffma2(w2, v0, acc[c][0]);
                acc[c][1] = ffma2(w2, v1, acc[c][1]);
                acc[c][2] = ffma2(w2, v2, acc[c][2]);
                acc[c][3] = ffma2(w2, v3, acc[c][3]);
            }
        }
        #pragma unroll
        for (int o = 4; o <= 16; o <<= 1) {
            #pragma unroll
            for (int c = 0; c < 2; c++) {
                #pragma unroll
                for (int i = 0; i < 4; i++) {
                    acc[c][i].x += __shfl_xor_sync(0xffffffffu, acc[c][i].x, o);
                    acc[c][i].y += __shfl_xor_sync(0xffffffffu, acc[c][i].y, o);
                }
            }
        }
        if (gg == 0) {
            #pragma unroll
            for (int c = 0; c < 2; c++) {
                int tok = (2*(gi0 + a) + ri) * WW + 2*(gj0 + c) + rj;
                float iv = inv[a*2 + c];
                __nv_bfloat162 o0 = __floats2bfloat162_rn(acc[c][0].x*iv, acc[c][0].y*iv);
                __nv_bfloat162 o1 = __floats2bfloat162_rn(acc[c][1].x*iv, acc[c][1].y*iv);
                __nv_bfloat162 o2 = __floats2bfloat162_rn(acc[c][2].x*iv, acc[c][2].y*iv);
                __nv_bfloat162 o3 = __floats2bfloat162_rn(acc[c][3].x*iv, acc[c][3].y*iv);
                uint4 pk = make_uint4(*reinterpret_cast<uint32_t*>(&o0),
                                      *reinterpret_cast<uint32_t*>(&o1),
                                      *reinterpret_cast<uint32_t*>(&o2),
                                      *reinterpret_cast<uint32_t*>(&o3));
                *reinterpret_cast<uint4*>(ctx + (size_t)tok*CC + choff) = pk;
            }
        }
    }
}

// ---------------- launch ----------------
extern "C" void kernel_launch(void* const* d_in, const int* in_sizes, int n_in,
                              void* d_out, int out_size)
{
    const float* x     = (const float*)d_in[0];
    const float* ln1_g = (const float*)d_in[1];
    const float* ln1_b = (const float*)d_in[2];
    const float* wq    = (const float*)d_in[3];
    const float* bq    = (const float*)d_in[4];
    const float* wk    = (const float*)d_in[5];
    const float* bk    = (const float*)d_in[6];
    const float* wv    = (const float*)d_in[7];
    const float* bv    = (const float*)d_in[8];
    const float* rpb   = (const float*)d_in[9];
    const float* wo    = (const float*)d_in[10];
    const float* bo    = (const float*)d_in[11];
    const float* ln2_g = (const float*)d_in[12];
    const float* ln2_b = (const float*)d_in[13];
    const float* w1    = (const float*)d_in[14];
    const float* b1    = (const float*)d_in[15];
    const float* w2    = (const float*)d_in[16];
    const float* b2    = (const float*)d_in[17];
    float* out = (float*)d_out;

    __nv_bfloat16 *hs, *kq, *vq, *ctxp, *y, *t;
    __nv_bfloat16 *wqkv_b, *wo_b, *w1_b, *w2_b;
    float *qq, *hs2, *bqkv;
    cudaGetSymbolAddress((void**)&hs,     g_hs);
    cudaGetSymbolAddress((void**)&qq,     g_q);
    cudaGetSymbolAddress((void**)&kq,     g_k);
    cudaGetSymbolAddress((void**)&vq,     g_v);
    cudaGetSymbolAddress((void**)&ctxp,   g_ctx);
    cudaGetSymbolAddress((void**)&hs2,    g_hs2);
    cudaGetSymbolAddress((void**)&y,      g_y);
    cudaGetSymbolAddress((void**)&t,      g_t);
    cudaGetSymbolAddress((void**)&wqkv_b, g_wqkv_b);
    cudaGetSymbolAddress((void**)&wo_b,   g_wo_b);
    cudaGetSymbolAddress((void**)&w1_b,   g_w1_b);
    cudaGetSymbolAddress((void**)&w2_b,   g_w2_b);
    cudaGetSymbolAddress((void**)&bqkv,   g_bqkv);

    // 1) pack weights to bf16 (vectorized)
    pack_kernel<<<768, 256>>>(wq, wk, wv, wo, w1, w2, bq, bk, bv);

    // 2) LN1 -> bf16
    ln_kernel<<<NTOK/8, 256>>>(x, ln1_g, ln1_b, hs);

    // 3) QKV GEMM: [4096,256] @ [256,768] -> q fp32(scaled) | k bf16 | v bf16
    {
        dim3 grid(768/64, NTOK/64);
        bgemm_kernel<3, float><<<grid, 256>>>(hs, wqkv_b, bqkv, nullptr, qq,
                                              kq, vq, NTOK, 768, CC);
    }

    // 4) attention -> bf16 ctx (quad-token blocks)
    {
        dim3 blk(32, HEADS);
        attn_kernel<<<1024, blk>>>(qq, kq, vq, rpb, ctxp);
    }

    // 5) wo GEMM + residual(x): hs2 = ctx@wo + bo + x  (fp32)
    {
        dim3 grid(CC/64, NTOK/64);
        bgemm_kernel<2, float><<<grid, 256>>>(ctxp, wo_b, bo, x, hs2,
                                              nullptr, nullptr, NTOK, CC, CC);
    }

    // 6) LN2 -> bf16
    ln_kernel<<<NTOK/8, 256>>>(hs2, ln2_g, ln2_b, y);

    // 7) w1 GEMM + exact GELU -> bf16 t
    {
        dim3 grid(FF/64, NTOK/64);
        bgemm_kernel<1, __nv_bfloat16><<<grid, 256>>>(y, w1_b, b1, nullptr, t,
                                                      nullptr, nullptr, NTOK, FF, CC);
    }

    // 8) w2 GEMM + residual(hs2): out = t@w2 + b2 + hs2  (fp32)
    {
        dim3 grid(CC/64, NTOK/64);
        bgemm_kernel<2, float><<<grid, 256>>>(t, w2_b, b2, hs2, out,
                                              nullptr, nullptr, NTOK, CC, FF);
    }
}

// round 14
// speedup vs baseline: 1.0900x; 1.0900x over previous
#include <cuda_runtime.h>
#include <cuda_bf16.h>
#include <math.h>
#include <stdint.h>

// Problem constants
#define BB 1
#define HH 64
#define WW 64
#define CC 256
#define HEADS 8
#define HD 32
#define KK 7
#define DIL 2
#define FF 1024
#define NTOK (HH*WW)            // 4096
#define SCALE 0.17677669529663687f  // 1/sqrt(32)

// ---------------- scratch (device globals; no runtime alloc) ----------------
__device__ __nv_bfloat16 g_hs [NTOK*CC];     // LN1(x), bf16 (GEMM A)
__device__ float         g_q  [NTOK*CC];     // q fp32, pre-scaled
__device__ __nv_bfloat16 g_k  [NTOK*CC];     // k bf16
__device__ __nv_bfloat16 g_v  [NTOK*CC];     // v bf16
__device__ __nv_bfloat16 g_ctx[NTOK*CC];     // attention context, bf16
__device__ float         g_hs2[NTOK*CC];     // x + attn_out, fp32
__device__ __nv_bfloat16 g_y  [NTOK*CC];     // LN2(hs2), bf16
__device__ __nv_bfloat16 g_t  [NTOK*FF];     // gelu(y@w1+b1), bf16
// bf16 weights, plain [k][n] layout
__device__ __nv_bfloat16 g_wqkv_b[256*768];
__device__ __nv_bfloat16 g_wo_b  [256*256];
__device__ __nv_bfloat16 g_w1_b  [256*1024];
__device__ __nv_bfloat16 g_w2_b  [1024*256];
__device__ float         g_bqkv  [768];

__device__ __forceinline__ float4 ld4(const float* p) {
    return *reinterpret_cast<const float4*>(p);
}
__device__ __forceinline__ float2 bf2f(uint32_t u) {
    __nv_bfloat162 h = *reinterpret_cast<__nv_bfloat162*>(&u);
    return __bfloat1622float2(h);
}
__device__ __forceinline__ float2 ffma2(float2 a, float2 b, float2 c) {
    float2 d;
    asm("fma.rn.f32x2 %0, %1, %2, %3;"
        : "=l"(*reinterpret_cast<uint64_t*>(&d))
        : "l"(*reinterpret_cast<const uint64_t*>(&a)),
          "l"(*reinterpret_cast<const uint64_t*>(&b)),
          "l"(*reinterpret_cast<const uint64_t*>(&c)));
    return d;
}
__device__ __forceinline__ float2 fmul2(float2 a, float2 b) {
    float2 d;
    asm("mul.rn.f32x2 %0, %1, %2;"
        : "=l"(*reinterpret_cast<uint64_t*>(&d))
        : "l"(*reinterpret_cast<const uint64_t*>(&a)),
          "l"(*reinterpret_cast<const uint64_t*>(&b)));
    return d;
}
__device__ __forceinline__ uint32_t smem_u32(const void* p) {
    uint32_t a;
    asm("{ .reg .u64 t; cvta.to.shared.u64 t, %1; cvt.u32.u64 %0, t; }"
        : "=r"(a) : "l"(p));
    return a;
}
__device__ __forceinline__ void ldsm_x4(uint32_t (&r)[4], uint32_t addr) {
    asm volatile("ldmatrix.sync.aligned.m8n8.x4.shared.b16 {%0,%1,%2,%3}, [%4];"
        : "=r"(r[0]), "=r"(r[1]), "=r"(r[2]), "=r"(r[3]) : "r"(addr));
}
__device__ __forceinline__ void ldsm_x4_t(uint32_t (&r)[4], uint32_t addr) {
    asm volatile("ldmatrix.sync.aligned.m8n8.x4.trans.shared.b16 {%0,%1,%2,%3}, [%4];"
        : "=r"(r[0]), "=r"(r[1]), "=r"(r[2]), "=r"(r[3]) : "r"(addr));
}
__device__ __forceinline__ void mma_bf16(float (&d)[4], const uint32_t (&a)[4],
                                         const uint32_t (&b)[2]) {
    asm volatile(
        "mma.sync.aligned.m16n8k16.row.col.f32.bf16.bf16.f32 "
        "{%0,%1,%2,%3}, {%4,%5,%6,%7}, {%8,%9}, {%0,%1,%2,%3};\n"
        : "+f"(d[0]), "+f"(d[1]), "+f"(d[2]), "+f"(d[3])
        : "r"(a[0]), "r"(a[1]), "r"(a[2]), "r"(a[3]),
          "r"(b[0]), "r"(b[1]));
}
__device__ __forceinline__ void cpa16(uint32_t dst, const void* src) {
    asm volatile("cp.async.cg.shared.global [%0], [%1], 16;"
        :: "r"(dst), "l"(src) : "memory");
}
#define CP_COMMIT() asm volatile("cp.async.commit_group;" ::: "memory")
#define CP_WAIT(n)  asm volatile("cp.async.wait_group %0;" :: "n"(n) : "memory")

// ---------------- weight pack: fp32 -> bf16 plain [k][n], vectorized --------
__device__ __forceinline__ uint2 f4_to_bf4(float4 v) {
    __nv_bfloat162 h0 = __floats2bfloat162_rn(v.x, v.y);
    __nv_bfloat162 h1 = __floats2bfloat162_rn(v.z, v.w);
    return make_uint2(*reinterpret_cast<uint32_t*>(&h0),
                      *reinterpret_cast<uint32_t*>(&h1));
}

__global__ void pack_kernel(const float* __restrict__ wq, const float* __restrict__ wk,
                            const float* __restrict__ wv, const float* __restrict__ wo,
                            const float* __restrict__ w1, const float* __restrict__ w2,
                            const float* __restrict__ bq, const float* __restrict__ bk,
                            const float* __restrict__ bv)
{
    int i4 = blockIdx.x * 256 + threadIdx.x;     // vector (4-elem) index
    if (i4 < 49152) {                            // wqkv: 256x768
        int idx = i4 * 4;
        int k = idx / 768, n = idx % 768;
        const float* W; int nn;
        if      (n < 256) { W = wq; nn = n; }
        else if (n < 512) { W = wk; nn = n - 256; }
        else              { W = wv; nn = n - 512; }
        float4 v = ld4(W + (size_t)k * 256 + nn);
        *reinterpret_cast<uint2*>(g_wqkv_b + idx) = f4_to_bf4(v);
    } else if (i4 < 65536) {                     // wo
        int t = (i4 - 49152) * 4;
        *reinterpret_cast<uint2*>(g_wo_b + t) = f4_to_bf4(ld4(wo + t));
    } else if (i4 < 131072) {                    // w1
        int t = (i4 - 65536) * 4;
        *reinterpret_cast<uint2*>(g_w1_b + t) = f4_to_bf4(ld4(w1 + t));
    } else if (i4 < 196608) {                    // w2
        int t = (i4 - 131072) * 4;
        *reinterpret_cast<uint2*>(g_w2_b + t) = f4_to_bf4(ld4(w2 + t));
    }
    if (i4 < 768) {
        float v;
        if      (i4 < 256) v = bq[i4];
        else if (i4 < 512) v = bk[i4 - 256];
        else               v = bv[i4 - 512];
        g_bqkv[i4] = v;
    }
}

// ---------------- LayerNorm: one warp per row, 8 rows/block ----------------
__global__ void ln_kernel(const float* __restrict__ x, const float* __restrict__ g,
                          const float* __restrict__ b, __nv_bfloat16* __restrict__ out)
{
    const int row  = blockIdx.x * 8 + (threadIdx.x >> 5);
    const int lane = threadIdx.x & 31;
    const float* xr = x + (size_t)row * CC + lane * 8;
    float4 v0 = ld4(xr), v1 = ld4(xr + 4);
    float s  = v0.x + v0.y + v0.z + v0.w + v1.x + v1.y + v1.z + v1.w;
    float sq = v0.x*v0.x + v0.y*v0.y + v0.z*v0.z + v0.w*v0.w
             + v1.x*v1.x + v1.y*v1.y + v1.z*v1.z + v1.w*v1.w;
    #pragma unroll
    for (int o = 16; o; o >>= 1) {
        s  += __shfl_xor_sync(0xffffffffu, s,  o);
        sq += __shfl_xor_sync(0xffffffffu, sq, o);
    }
    float mean = s * (1.0f/CC);
    float var  = sq * (1.0f/CC) - mean*mean;
    float inv  = rsqrtf(var + 1e-5f);
    float4 g0 = ld4(g + lane*8), g1 = ld4(g + lane*8 + 4);
    float4 b0 = ld4(b + lane*8), b1 = ld4(b + lane*8 + 4);
    __nv_bfloat162 o0 = __floats2bfloat162_rn((v0.x-mean)*inv*g0.x + b0.x,
                                              (v0.y-mean)*inv*g0.y + b0.y);
    __nv_bfloat162 o1 = __floats2bfloat162_rn((v0.z-mean)*inv*g0.z + b0.z,
                                              (v0.w-mean)*inv*g0.w + b0.w);
    __nv_bfloat162 o2 = __floats2bfloat162_rn((v1.x-mean)*inv*g1.x + b1.x,
                                              (v1.y-mean)*inv*g1.y + b1.y);
    __nv_bfloat162 o3 = __floats2bfloat162_rn((v1.z-mean)*inv*g1.z + b1.z,
                                              (v1.w-mean)*inv*g1.w + b1.w);
    uint4 pk = make_uint4(*reinterpret_cast<uint32_t*>(&o0),
                          *reinterpret_cast<uint32_t*>(&o1),
                          *reinterpret_cast<uint32_t*>(&o2),
                          *reinterpret_cast<uint32_t*>(&o3));
    *reinterpret_cast<uint4*>(out + (size_t)row * CC + lane * 8) = pk;
}

// ---------------- bf16 tensor-core GEMM: cp.async 4-stage pipeline ----------
// BM64 tiles: 2Mx4N warps, warp 32x16 (2x2 frags), minctas=3.
// EPI 1: gelu(+bias) ; EPI 2: +bias + res ; EPI 3: qkv split
#define A_STR 20   // uint32 per A row (80B)
#define B_STR 36   // uint32 per B row (144B)
#define NSTG 4
#define BMT 64

__device__ __forceinline__ void store2(float* p, float v0, float v1) {
    *reinterpret_cast<float2*>(p) = make_float2(v0, v1);
}
__device__ __forceinline__ void store2(__nv_bfloat16* p, float v0, float v1) {
    *reinterpret_cast<__nv_bfloat162*>(p) = __floats2bfloat162_rn(v0, v1);
}

template<int EPI, typename OutT>
__global__ void __launch_bounds__(256, 3)
bgemm_kernel(const __nv_bfloat16* __restrict__ A, const __nv_bfloat16* __restrict__ W,
             const float* __restrict__ bias, const float* __restrict__ res,
             OutT* __restrict__ C, __nv_bfloat16* __restrict__ kout,
             __nv_bfloat16* __restrict__ vout, int M, int N, int K)
{
    constexpr int WM = 2, WN = 4, NF = 2;
    constexpr uint32_t A_STG = BMT * A_STR * 4;
    constexpr uint32_t B_STG = 32 * B_STR * 4;

    __shared__ __align__(16) uint32_t As[NSTG][BMT * A_STR];
    __shared__ __align__(16) uint32_t Bs[NSTG][32 * B_STR];

    const int tid  = threadIdx.x;
    const int lane = tid & 31, warp = tid >> 5;
    const int wm = warp % WM, wn = warp / WM;
    const int g = lane >> 2, c = lane & 3;
    const int bm = blockIdx.y * BMT, bn = blockIdx.x * 64;

    const int arow = (tid >> 1) & 63, ahalf = (tid & 1);
    const bool aload = (tid < 128);
    const int bkrow = tid >> 3, bnch = (tid & 7) * 8;
    const __nv_bfloat16* Ag = A + (size_t)(bm + arow) * K + ahalf * 16;
    const __nv_bfloat16* Wg = W + (size_t)bkrow * N + bn + bnch;

    const uint32_t aBase = smem_u32(As);
    const uint32_t bBase = smem_u32(Bs);
    const uint32_t asto = (uint32_t)(arow * A_STR + ahalf * 8) * 4;
    const uint32_t bsto = (uint32_t)(bkrow * B_STR + (tid & 7) * 4) * 4;

    const uint32_t aoff = (uint32_t)(wm*32 + (lane & 15)) * 80 + (lane >> 4) * 16;
    const uint32_t boff = (uint32_t)(lane & 15) * 144 +
                          (uint32_t)(wn*(NF*8) + (lane >> 4)*8) * 2;

    float acc[2][NF][4];
    #pragma unroll
    for (int mf = 0; mf < 2; mf++)
        #pragma unroll
        for (int nf = 0; nf < NF; nf++)
            #pragma unroll
            for (int e = 0; e < 4; e++) acc[mf][nf][e] = 0.f;

    const int NT = K / 32;

    auto issue = [&](int kt, int s) {
        if (aload) {
            const __nv_bfloat16* ag = Ag + kt * 32;
            uint32_t d = aBase + (uint32_t)s * A_STG + asto;
            cpa16(d, ag);
            cpa16(d + 16, ag + 8);
        }
        cpa16(bBase + (uint32_t)s * B_STG + bsto, Wg + (size_t)kt * 32 * N);
        CP_COMMIT();
    };

    // prologue: NSTG-1 stages in flight
    #pragma unroll
    for (int p = 0; p < NSTG - 1; p++) issue(p, p);

    for (int kt = 0; kt < NT; kt++) {
        CP_WAIT(NSTG - 2);
        __syncthreads();
        const int s = kt % NSTG;
        if (kt + NSTG - 1 < NT) {
            issue(kt + NSTG - 1, (kt + NSTG - 1) % NSTG);
        } else {
            CP_COMMIT();   // empty group keeps wait_group invariant at the tail
        }

        const uint32_t ab = aBase + (uint32_t)s * A_STG;
        const uint32_t bb = bBase + (uint32_t)s * B_STG;
        #pragma unroll
        for (int ks = 0; ks < 32; ks += 16) {
            uint32_t af[2][4], bf[NF][2];
            #pragma unroll
            for (int mf = 0; mf < 2; mf++)
                ldsm_x4(af[mf], ab + aoff + (uint32_t)(mf * 16 * 80 + ks * 2));
            {
                uint32_t br[4];
                ldsm_x4_t(br, bb + boff + (uint32_t)(ks * 144));
                bf[0][0] = br[0]; bf[0][1] = br[1];
                bf[1][0] = br[2]; bf[1][1] = br[3];
            }
            #pragma unroll
            for (int mf = 0; mf < 2; mf++)
                #pragma unroll
                for (int nf = 0; nf < NF; nf++)
                    mma_bf16(acc[mf][nf], af[mf], bf[nf]);
        }
    }
    __syncthreads();

    #pragma unroll
    for (int mf = 0; mf < 2; mf++) {
        #pragma unroll
        for (int nf = 0; nf < NF; nf++) {
            int row0 = bm + wm * 32 + mf * 16 + g;
            int col  = bn + wn * (NF*8) + nf * 8 + c * 2;
            float bx = bias[col], by = bias[col + 1];
            #pragma unroll
            for (int h = 0; h < 2; h++) {
                int row = row0 + h * 8;
                float v0 = acc[mf][nf][h * 2 + 0] + bx;
                float v1 = acc[mf][nf][h * 2 + 1] + by;
                if (EPI == 1) {
                    v0 *= normcdff(v0);
                    v1 *= normcdff(v1);
                } else if (EPI == 2) {
                    float2 r = *reinterpret_cast<const float2*>(res + (size_t)row * N + col);
                    v0 += r.x; v1 += r.y;
                }
                if (EPI == 3) {
                    if (col < 256) {
                        store2((float*)C + (size_t)row * 256 + col, v0 * SCALE, v1 * SCALE);
                    } else if (col < 512) {
                        store2(kout + (size_t)row * 256 + (col - 256), v0, v1);
                    } else {
                        store2(vout + (size_t)row * 256 + (col - 512), v0, v1);
                    }
                } else {
                    store2(C + (size_t)row * N + col, v0, v1);
                }
            }
        }
    }
}

// ---------------- dilated neighborhood attention: quad-token sharing --------
// (R12 version — instruction-throughput optimal: full unroll, 4 queries live)
__global__ void __launch_bounds__(256)
attn_kernel(const float* __restrict__ q, const __nv_bfloat16* __restrict__ k,
            const __nv_bfloat16* __restrict__ v, const float* __restrict__ rpb,
            __nv_bfloat16* __restrict__ ctx)
{
    __shared__ float sc[HEADS][4][64];

    const int head = threadIdx.y;
    const int lane = threadIdx.x;
    const int gg = lane >> 2, e = lane & 3;

    const int b   = blockIdx.x;
    const int bi  = b & 15, bj = (b >> 4) & 15, par = b >> 8;
    const int ri  = par & 1, rj = par >> 1;
    const int gi0 = bi * 2, gj0 = bj * 2;

    int si0 = gi0 - 3; si0 = si0 < 0 ? 0 : (si0 > 25 ? 25 : si0);
    int si1 = gi0 - 2; si1 = si1 < 0 ? 0 : (si1 > 25 ? 25 : si1);
    int sj0 = gj0 - 3; sj0 = sj0 < 0 ? 0 : (sj0 > 25 ? 25 : sj0);
    int sj1 = gj0 - 2; sj1 = sj1 < 0 ? 0 : (sj1 > 25 ? 25 : sj1);
    const int dr1 = si1 - si0, dc1 = sj1 - sj0;

    int sjg = sj0 + gg; sjg = sjg > 31 ? 31 : sjg;
    const int kj = sjg * 2 + rj;
    const int choff = head * HD + e * 8;
    const int kcoff = kj * CC + choff;

    float2 qv[4][4];
    int toks[4];
    #pragma unroll
    for (int a = 0; a < 2; a++) {
        #pragma unroll
        for (int c = 0; c < 2; c++) {
            int tok = (2*(gi0 + a) + ri) * WW + 2*(gj0 + c) + rj;
            int qq_ = a*2 + c;
            toks[qq_] = tok;
            const float* qp = q + (size_t)tok * CC + choff;
            float4 qa = ld4(qp), qb = ld4(qp + 4);
            qv[qq_][0] = make_float2(qa.x, qa.y);
            qv[qq_][1] = make_float2(qa.z, qa.w);
            qv[qq_][2] = make_float2(qb.x, qb.y);
            qv[qq_][3] = make_float2(qb.z, qb.w);
        }
    }

    #pragma unroll
    for (int t = 0; t < 8; t++) {
        int sit = si0 + t; sit = sit > 31 ? 31 : sit;
        const int ki = sit * 2 + ri;
        uint4 u = *reinterpret_cast<const uint4*>(k + ki * (WW*CC) + kcoff);
        float2 k0 = bf2f(u.x), k1 = bf2f(u.y), k2 = bf2f(u.z), k3 = bf2f(u.w);
        #pragma unroll
        for (int qq_ = 0; qq_ < 4; qq_++) {
            float2 p2 = fmul2(qv[qq_][0], k0);
            p2 = ffma2(qv[qq_][1], k1, p2);
            p2 = ffma2(qv[qq_][2], k2, p2);
            p2 = ffma2(qv[qq_][3], k3, p2);
            float pt = p2.x + p2.y;
            pt += __shfl_xor_sync(0xffffffffu, pt, 1);
            pt += __shfl_xor_sync(0xffffffffu, pt, 2);
            if (e == 0) sc[head][qq_][t*8 + gg] = pt;
        }
    }
    __syncwarp();

    const float* br = rpb + head * 169;
    float inv[4];
    #pragma unroll
    for (int qq_ = 0; qq_ < 4; qq_++) {
        const int a = qq_ >> 1, c = qq_ & 1;
        const int dra = a ? dr1 : 0, dcc = c ? dc1 : 0;
        const int Bq = (si0 - gi0 - a + 6) * 13 + (sj0 - gj0 - c + 6);
        float s1, s2;
        {
            int p = lane, pr = p >> 3, pc = p & 7;
            bool val = (pr >= dra) && (pr < dra + 7) && (pc >= dcc) && (pc < dcc + 7);
            s1 = val ? sc[head][qq_][p] + br[Bq + pr*13 + pc] : -1e30f;
        }
        {
            int p = lane + 32, pr = p >> 3, pc = p & 7;
            bool val = (pr >= dra) && (pr < dra + 7) && (pc >= dcc) && (pc < dcc + 7);
            s2 = val ? sc[head][qq_][p] + br[Bq + pr*13 + pc] : -1e30f;
        }
        float m = fmaxf(s1, s2);
        #pragma unroll
        for (int o = 16; o; o >>= 1) m = fmaxf(m, __shfl_xor_sync(0xffffffffu, m, o));
        float e1 = __expf(s1 - m), e2 = __expf(s2 - m);
        float ss = e1 + e2;
        #pragma unroll
        for (int o = 16; o; o >>= 1) ss += __shfl_xor_sync(0xffffffffu, ss, o);
        sc[head][qq_][lane]      = e1;
        sc[head][qq_][lane + 32] = e2;
        inv[qq_] = 1.0f / ss;
    }
    __syncwarp();

    float2 acc[4][4];
    #pragma unroll
    for (int qq_ = 0; qq_ < 4; qq_++)
        #pragma unroll
        for (int i = 0; i < 4; i++) acc[qq_][i] = make_float2(0.f, 0.f);

    #pragma unroll
    for (int t = 0; t < 8; t++) {
        int sit = si0 + t; sit = sit > 31 ? 31 : sit;
        const int ki = sit * 2 + ri;
        uint4 u = *reinterpret_cast<const uint4*>(v + ki * (WW*CC) + kcoff);
        float2 v0 = bf2f(u.x), v1 = bf2f(u.y), v2 = bf2f(u.z), v3 = bf2f(u.w);
        #pragma unroll
        for (int qq_ = 0; qq_ < 4; qq_++) {
            float w = sc[head][qq_][t*8 + gg];
            float2 w2 = make_float2(w, w);
            acc[qq_][0] = ffma2(w2, v0, acc[qq_][0]);
            acc[qq_][1] = ffma2(w2, v1, acc[qq_][1]);
            acc[qq_][2] = ffma2(w2, v2, acc[qq_][2]);
            acc[qq_][3] = ffma2(w2, v3, acc[qq_][3]);
        }
    }

    #pragma unroll
    for (int o = 4; o <= 16; o <<= 1) {
        #pragma unroll
        for (int qq_ = 0; qq_ < 4; qq_++) {
            #pragma unroll
            for (int i = 0; i < 4; i++) {
                acc[qq_][i].x += __shfl_xor_sync(0xffffffffu, acc[qq_][i].x, o);
                acc[qq_][i].y += __shfl_xor_sync(0xffffffffu, acc[qq_][i].y, o);
            }
        }
    }
    if (gg == 0) {
        #pragma unroll
        for (int qq_ = 0; qq_ < 4; qq_++) {
            float iv = inv[qq_];
            __nv_bfloat162 o0 = __floats2bfloat162_rn(acc[qq_][0].x*iv, acc[qq_][0].y*iv);
            __nv_bfloat162 o1 = __floats2bfloat162_rn(acc[qq_][1].x*iv, acc[qq_][1].y*iv);
            __nv_bfloat162 o2 = __floats2bfloat162_rn(acc[qq_][2].x*iv, acc[qq_][2].y*iv);
            __nv_bfloat162 o3 = __floats2bfloat162_rn(acc[qq_][3].x*iv, acc[qq_][3].y*iv);
            uint4 pk = make_uint4(*reinterpret_cast<uint32_t*>(&o0),
                                  *reinterpret_cast<uint32_t*>(&o1),
                                  *reinterpret_cast<uint32_t*>(&o2),
                                  *reinterpret_cast<uint32_t*>(&o3));
            *reinterpret_cast<uint4*>(ctx + (size_t)toks[qq_]*CC + choff) = pk;
        }
    }
}

// ---------------- launch ----------------
extern "C" void kernel_launch(void* const* d_in, const int* in_sizes, int n_in,
                              void* d_out, int out_size)
{
    const float* x     = (const float*)d_in[0];
    const float* ln1_g = (const float*)d_in[1];
    const float* ln1_b = (const float*)d_in[2];
    const float* wq    = (const float*)d_in[3];
    const float* bq    = (const float*)d_in[4];
    const float* wk    = (const float*)d_in[5];
    const float* bk    = (const float*)d_in[6];
    const float* wv    = (const float*)d_in[7];
    const float* bv    = (const float*)d_in[8];
    const float* rpb   = (const float*)d_in[9];
    const float* wo    = (const float*)d_in[10];
    const float* bo    = (const float*)d_in[11];
    const float* ln2_g = (const float*)d_in[12];
    const float* ln2_b = (const float*)d_in[13];
    const float* w1    = (const float*)d_in[14];
    const float* b1    = (const float*)d_in[15];
    const float* w2    = (const float*)d_in[16];
    const float* b2    = (const float*)d_in[17];
    float* out = (float*)d_out;

    __nv_bfloat16 *hs, *kq, *vq, *ctxp, *y, *t;
    __nv_bfloat16 *wqkv_b, *wo_b, *w1_b, *w2_b;
    float *qq, *hs2, *bqkv;
    cudaGetSymbolAddress((void**)&hs,     g_hs);
    cudaGetSymbolAddress((void**)&qq,     g_q);
    cudaGetSymbolAddress((void**)&kq,     g_k);
    cudaGetSymbolAddress((void**)&vq,     g_v);
    cudaGetSymbolAddress((void**)&ctxp,   g_ctx);
    cudaGetSymbolAddress((void**)&hs2,    g_hs2);
    cudaGetSymbolAddress((void**)&y,      g_y);
    cudaGetSymbolAddress((void**)&t,      g_t);
    cudaGetSymbolAddress((void**)&wqkv_b, g_wqkv_b);
    cudaGetSymbolAddress((void**)&wo_b,   g_wo_b);
    cudaGetSymbolAddress((void**)&w1_b,   g_w1_b);
    cudaGetSymbolAddress((void**)&w2_b,   g_w2_b);
    cudaGetSymbolAddress((void**)&bqkv,   g_bqkv);

    // 1) pack weights to bf16 (vectorized)
    pack_kernel<<<768, 256>>>(wq, wk, wv, wo, w1, w2, bq, bk, bv);

    // 2) LN1 -> bf16
    ln_kernel<<<NTOK/8, 256>>>(x, ln1_g, ln1_b, hs);

    // 3) QKV GEMM: [4096,256] @ [256,768] -> q fp32(scaled) | k bf16 | v bf16
    {
        dim3 grid(768/64, NTOK/64);
        bgemm_kernel<3, float><<<grid, 256>>>(hs, wqkv_b, bqkv, nullptr, qq,
                                              kq, vq, NTOK, 768, CC);
    }

    // 4) attention -> bf16 ctx (quad-token blocks)
    {
        dim3 blk(32, HEADS);
        attn_kernel<<<1024, blk>>>(qq, kq, vq, rpb, ctxp);
    }

    // 5) wo GEMM + residual(x): hs2 = ctx@wo + bo + x  (fp32)
    {
        dim3 grid(CC/64, NTOK/64);
        bgemm_kernel<2, float><<<grid, 256>>>(ctxp, wo_b, bo, x, hs2,
                                              nullptr, nullptr, NTOK, CC, CC);
    }

    // 6) LN2 -> bf16
    ln_kernel<<<NTOK/8, 256>>>(hs2, ln2_g, ln2_b, y);

    // 7) w1 GEMM + exact GELU -> bf16 t
    {
        dim3 grid(FF/64, NTOK/64);
        bgemm_kernel<1, __nv_bfloat16><<<grid, 256>>>(y, w1_b, b1, nullptr, t,
                                                      nullptr, nullptr, NTOK, FF, CC);
    }

    // 8) w2 GEMM + residual(hs2): out = t@w2 + b2 + hs2  (fp32)
    {
        dim3 grid(CC/64, NTOK/64);
        bgemm_kernel<2, float><<<grid, 256>>>(t, w2_b, b2, hs2, out,
                                              nullptr, nullptr, NTOK, CC, FF);
    }
}

// round 15
// speedup vs baseline: 1.1156x; 1.0234x over previous
#include <cuda_runtime.h>
#include <cuda_bf16.h>
#include <math.h>
#include <stdint.h>

// Problem constants
#define BB 1
#define HH 64
#define WW 64
#define CC 256
#define HEADS 8
#define HD 32
#define KK 7
#define DIL 2
#define FF 1024
#define NTOK (HH*WW)            // 4096
#define SCALE 0.17677669529663687f  // 1/sqrt(32)

// ---------------- scratch (device globals; no runtime alloc) ----------------
__device__ __nv_bfloat16 g_hs [NTOK*CC];     // LN1(x), bf16 (GEMM A)
__device__ float         g_q  [NTOK*CC];     // q fp32, pre-scaled
__device__ __nv_bfloat16 g_k  [NTOK*CC];     // k bf16
__device__ __nv_bfloat16 g_v  [NTOK*CC];     // v bf16
__device__ __nv_bfloat16 g_ctx[NTOK*CC];     // attention context, bf16
__device__ float         g_hs2[NTOK*CC];     // x + attn_out, fp32
__device__ __nv_bfloat16 g_y  [NTOK*CC];     // LN2(hs2), bf16
__device__ __nv_bfloat16 g_t  [NTOK*FF];     // gelu(y@w1+b1), bf16
// bf16 weights, plain [k][n] layout
__device__ __nv_bfloat16 g_wqkv_b[256*768];
__device__ __nv_bfloat16 g_wo_b  [256*256];
__device__ __nv_bfloat16 g_w1_b  [256*1024];
__device__ __nv_bfloat16 g_w2_b  [1024*256];
__device__ float         g_bqkv  [768];

__device__ __forceinline__ float4 ld4(const float* p) {
    return *reinterpret_cast<const float4*>(p);
}
__device__ __forceinline__ float2 bf2f(uint32_t u) {
    __nv_bfloat162 h = *reinterpret_cast<__nv_bfloat162*>(&u);
    return __bfloat1622float2(h);
}
__device__ __forceinline__ float2 ffma2(float2 a, float2 b, float2 c) {
    float2 d;
    asm("fma.rn.f32x2 %0, %1, %2, %3;"
        : "=l"(*reinterpret_cast<uint64_t*>(&d))
        : "l"(*reinterpret_cast<const uint64_t*>(&a)),
          "l"(*reinterpret_cast<const uint64_t*>(&b)),
          "l"(*reinterpret_cast<const uint64_t*>(&c)));
    return d;
}
__device__ __forceinline__ float2 fmul2(float2 a, float2 b) {
    float2 d;
    asm("mul.rn.f32x2 %0, %1, %2;"
        : "=l"(*reinterpret_cast<uint64_t*>(&d))
        : "l"(*reinterpret_cast<const uint64_t*>(&a)),
          "l"(*reinterpret_cast<const uint64_t*>(&b)));
    return d;
}
__device__ __forceinline__ uint32_t smem_u32(const void* p) {
    uint32_t a;
    asm("{ .reg .u64 t; cvta.to.shared.u64 t, %1; cvt.u32.u64 %0, t; }"
        : "=r"(a) : "l"(p));
    return a;
}
__device__ __forceinline__ void ldsm_x4(uint32_t (&r)[4], uint32_t addr) {
    asm volatile("ldmatrix.sync.aligned.m8n8.x4.shared.b16 {%0,%1,%2,%3}, [%4];"
        : "=r"(r[0]), "=r"(r[1]), "=r"(r[2]), "=r"(r[3]) : "r"(addr));
}
__device__ __forceinline__ void ldsm_x4_t(uint32_t (&r)[4], uint32_t addr) {
    asm volatile("ldmatrix.sync.aligned.m8n8.x4.trans.shared.b16 {%0,%1,%2,%3}, [%4];"
        : "=r"(r[0]), "=r"(r[1]), "=r"(r[2]), "=r"(r[3]) : "r"(addr));
}
__device__ __forceinline__ void mma_bf16(float (&d)[4], const uint32_t (&a)[4],
                                         const uint32_t (&b)[2]) {
    asm volatile(
        "mma.sync.aligned.m16n8k16.row.col.f32.bf16.bf16.f32 "
        "{%0,%1,%2,%3}, {%4,%5,%6,%7}, {%8,%9}, {%0,%1,%2,%3};\n"
        : "+f"(d[0]), "+f"(d[1]), "+f"(d[2]), "+f"(d[3])
        : "r"(a[0]), "r"(a[1]), "r"(a[2]), "r"(a[3]),
          "r"(b[0]), "r"(b[1]));
}
__device__ __forceinline__ void cpa16(uint32_t dst, const void* src) {
    asm volatile("cp.async.cg.shared.global [%0], [%1], 16;"
        :: "r"(dst), "l"(src) : "memory");
}
#define CP_COMMIT() asm volatile("cp.async.commit_group;" ::: "memory")
#define CP_WAIT(n)  asm volatile("cp.async.wait_group %0;" :: "n"(n) : "memory")

__device__ __forceinline__ uint2 f4_to_bf4(float4 v) {
    __nv_bfloat162 h0 = __floats2bfloat162_rn(v.x, v.y);
    __nv_bfloat162 h1 = __floats2bfloat162_rn(v.z, v.w);
    return make_uint2(*reinterpret_cast<uint32_t*>(&h0),
                      *reinterpret_cast<uint32_t*>(&h1));
}

// ---------------- LN row helper (one warp per row) ----------------
__device__ __forceinline__ void ln_row(const float* __restrict__ x,
                                       const float* __restrict__ g,
                                       const float* __restrict__ b,
                                       __nv_bfloat16* __restrict__ out,
                                       int row, int lane)
{
    const float* xr = x + (size_t)row * CC + lane * 8;
    float4 v0 = ld4(xr), v1 = ld4(xr + 4);
    float s  = v0.x + v0.y + v0.z + v0.w + v1.x + v1.y + v1.z + v1.w;
    float sq = v0.x*v0.x + v0.y*v0.y + v0.z*v0.z + v0.w*v0.w
             + v1.x*v1.x + v1.y*v1.y + v1.z*v1.z + v1.w*v1.w;
    #pragma unroll
    for (int o = 16; o; o >>= 1) {
        s  += __shfl_xor_sync(0xffffffffu, s,  o);
        sq += __shfl_xor_sync(0xffffffffu, sq, o);
    }
    float mean = s * (1.0f/CC);
    float var  = sq * (1.0f/CC) - mean*mean;
    float inv  = rsqrtf(var + 1e-5f);
    float4 g0 = ld4(g + lane*8), g1 = ld4(g + lane*8 + 4);
    float4 b0 = ld4(b + lane*8), b1 = ld4(b + lane*8 + 4);
    __nv_bfloat162 o0 = __floats2bfloat162_rn((v0.x-mean)*inv*g0.x + b0.x,
                                              (v0.y-mean)*inv*g0.y + b0.y);
    __nv_bfloat162 o1 = __floats2bfloat162_rn((v0.z-mean)*inv*g0.z + b0.z,
                                              (v0.w-mean)*inv*g0.w + b0.w);
    __nv_bfloat162 o2 = __floats2bfloat162_rn((v1.x-mean)*inv*g1.x + b1.x,
                                              (v1.y-mean)*inv*g1.y + b1.y);
    __nv_bfloat162 o3 = __floats2bfloat162_rn((v1.z-mean)*inv*g1.z + b1.z,
                                              (v1.w-mean)*inv*g1.w + b1.w);
    uint4 pk = make_uint4(*reinterpret_cast<uint32_t*>(&o0),
                          *reinterpret_cast<uint32_t*>(&o1),
                          *reinterpret_cast<uint32_t*>(&o2),
                          *reinterpret_cast<uint32_t*>(&o3));
    *reinterpret_cast<uint4*>(out + (size_t)row * CC + lane * 8) = pk;
}

// ---------------- fused LN1 + weight pack (independent work, one launch) ----
// blocks [0,512): LN1 of x (8 rows each). blocks [512,1280): weight packing.
__global__ void ln1_pack_kernel(const float* __restrict__ x,
                                const float* __restrict__ ln1_g, const float* __restrict__ ln1_b,
                                __nv_bfloat16* __restrict__ hs,
                                const float* __restrict__ wq, const float* __restrict__ wk,
                                const float* __restrict__ wv, const float* __restrict__ wo,
                                const float* __restrict__ w1, const float* __restrict__ w2,
                                const float* __restrict__ bq, const float* __restrict__ bk,
                                const float* __restrict__ bv)
{
    if (blockIdx.x < 512) {
        int row = blockIdx.x * 8 + (threadIdx.x >> 5);
        ln_row(x, ln1_g, ln1_b, hs, row, threadIdx.x & 31);
        return;
    }
    int i4 = (blockIdx.x - 512) * 256 + threadIdx.x;   // vector (4-elem) index
    if (i4 < 49152) {                            // wqkv: 256x768
        int idx = i4 * 4;
        int k = idx / 768, n = idx % 768;
        const float* W; int nn;
        if      (n < 256) { W = wq; nn = n; }
        else if (n < 512) { W = wk; nn = n - 256; }
        else              { W = wv; nn = n - 512; }
        float4 v = ld4(W + (size_t)k * 256 + nn);
        *reinterpret_cast<uint2*>(g_wqkv_b + idx) = f4_to_bf4(v);
    } else if (i4 < 65536) {                     // wo
        int t = (i4 - 49152) * 4;
        *reinterpret_cast<uint2*>(g_wo_b + t) = f4_to_bf4(ld4(wo + t));
    } else if (i4 < 131072) {                    // w1
        int t = (i4 - 65536) * 4;
        *reinterpret_cast<uint2*>(g_w1_b + t) = f4_to_bf4(ld4(w1 + t));
    } else if (i4 < 196608) {                    // w2
        int t = (i4 - 131072) * 4;
        *reinterpret_cast<uint2*>(g_w2_b + t) = f4_to_bf4(ld4(w2 + t));
    }
    if (i4 < 768) {
        float v;
        if      (i4 < 256) v = bq[i4];
        else if (i4 < 512) v = bk[i4 - 256];
        else               v = bv[i4 - 512];
        g_bqkv[i4] = v;
    }
}

// ---------------- LayerNorm standalone (LN2) ----------------
__global__ void ln_kernel(const float* __restrict__ x, const float* __restrict__ g,
                          const float* __restrict__ b, __nv_bfloat16* __restrict__ out)
{
    ln_row(x, g, b, out, blockIdx.x * 8 + (threadIdx.x >> 5), threadIdx.x & 31);
}

// ---------------- bf16 tensor-core GEMM: cp.async 3-stage pipeline ----------
// BM64 tiles: 2Mx4N warps, warp 32x16 (2x2 frags), minctas=3. (R12 config)
// EPI 1: gelu(+bias) ; EPI 2: +bias + res ; EPI 3: qkv split
#define A_STR 20   // uint32 per A row (80B)
#define B_STR 36   // uint32 per B row (144B)
#define NSTG 3
#define BMT 64

__device__ __forceinline__ void store2(float* p, float v0, float v1) {
    *reinterpret_cast<float2*>(p) = make_float2(v0, v1);
}
__device__ __forceinline__ void store2(__nv_bfloat16* p, float v0, float v1) {
    *reinterpret_cast<__nv_bfloat162*>(p) = __floats2bfloat162_rn(v0, v1);
}

template<int EPI, typename OutT>
__global__ void __launch_bounds__(256, 3)
bgemm_kernel(const __nv_bfloat16* __restrict__ A, const __nv_bfloat16* __restrict__ W,
             const float* __restrict__ bias, const float* __restrict__ res,
             OutT* __restrict__ C, __nv_bfloat16* __restrict__ kout,
             __nv_bfloat16* __restrict__ vout, int M, int N, int K)
{
    constexpr int WM = 2, WN = 4, NF = 2;
    constexpr uint32_t A_STG = BMT * A_STR * 4;
    constexpr uint32_t B_STG = 32 * B_STR * 4;

    __shared__ __align__(16) uint32_t As[NSTG][BMT * A_STR];
    __shared__ __align__(16) uint32_t Bs[NSTG][32 * B_STR];

    const int tid  = threadIdx.x;
    const int lane = tid & 31, warp = tid >> 5;
    const int wm = warp % WM, wn = warp / WM;
    const int g = lane >> 2, c = lane & 3;
    const int bm = blockIdx.y * BMT, bn = blockIdx.x * 64;

    const int arow = (tid >> 1) & 63, ahalf = (tid & 1);
    const bool aload = (tid < 128);
    const int bkrow = tid >> 3, bnch = (tid & 7) * 8;
    const __nv_bfloat16* Ag = A + (size_t)(bm + arow) * K + ahalf * 16;
    const __nv_bfloat16* Wg = W + (size_t)bkrow * N + bn + bnch;

    const uint32_t aBase = smem_u32(As);
    const uint32_t bBase = smem_u32(Bs);
    const uint32_t asto = (uint32_t)(arow * A_STR + ahalf * 8) * 4;
    const uint32_t bsto = (uint32_t)(bkrow * B_STR + (tid & 7) * 4) * 4;

    const uint32_t aoff = (uint32_t)(wm*32 + (lane & 15)) * 80 + (lane >> 4) * 16;
    const uint32_t boff = (uint32_t)(lane & 15) * 144 +
                          (uint32_t)(wn*(NF*8) + (lane >> 4)*8) * 2;

    float acc[2][NF][4];
    #pragma unroll
    for (int mf = 0; mf < 2; mf++)
        #pragma unroll
        for (int nf = 0; nf < NF; nf++)
            #pragma unroll
            for (int e = 0; e < 4; e++) acc[mf][nf][e] = 0.f;

    const int NT = K / 32;

    auto issue = [&](int kt, int s) {
        if (aload) {
            const __nv_bfloat16* ag = Ag + kt * 32;
            uint32_t d = aBase + (uint32_t)s * A_STG + asto;
            cpa16(d, ag);
            cpa16(d + 16, ag + 8);
        }
        cpa16(bBase + (uint32_t)s * B_STG + bsto, Wg + (size_t)kt * 32 * N);
        CP_COMMIT();
    };

    issue(0, 0);
    issue(1, 1);

    for (int kt = 0; kt < NT; kt++) {
        CP_WAIT(NSTG - 2);
        __syncthreads();
        const int s = kt % NSTG;
        if (kt + NSTG - 1 < NT) {
            issue(kt + NSTG - 1, (kt + NSTG - 1) % NSTG);
        } else {
            CP_COMMIT();   // empty group keeps wait_group invariant at the tail
        }

        const uint32_t ab = aBase + (uint32_t)s * A_STG;
        const uint32_t bb = bBase + (uint32_t)s * B_STG;
        #pragma unroll
        for (int ks = 0; ks < 32; ks += 16) {
            uint32_t af[2][4], bf[NF][2];
            #pragma unroll
            for (int mf = 0; mf < 2; mf++)
                ldsm_x4(af[mf], ab + aoff + (uint32_t)(mf * 16 * 80 + ks * 2));
            {
                uint32_t br[4];
                ldsm_x4_t(br, bb + boff + (uint32_t)(ks * 144));
                bf[0][0] = br[0]; bf[0][1] = br[1];
                bf[1][0] = br[2]; bf[1][1] = br[3];
            }
            #pragma unroll
            for (int mf = 0; mf < 2; mf++)
                #pragma unroll
                for (int nf = 0; nf < NF; nf++)
                    mma_bf16(acc[mf][nf], af[mf], bf[nf]);
        }
    }
    __syncthreads();

    #pragma unroll
    for (int mf = 0; mf < 2; mf++) {
        #pragma unroll
        for (int nf = 0; nf < NF; nf++) {
            int row0 = bm + wm * 32 + mf * 16 + g;
            int col  = bn + wn * (NF*8) + nf * 8 + c * 2;
            float bx = bias[col], by = bias[col + 1];
            #pragma unroll
            for (int h = 0; h < 2; h++) {
                int row = row0 + h * 8;
                float v0 = acc[mf][nf][h * 2 + 0] + bx;
                float v1 = acc[mf][nf][h * 2 + 1] + by;
                if (EPI == 1) {
                    v0 *= normcdff(v0);
                    v1 *= normcdff(v1);
                } else if (EPI == 2) {
                    float2 r = *reinterpret_cast<const float2*>(res + (size_t)row * N + col);
                    v0 += r.x; v1 += r.y;
                }
                if (EPI == 3) {
                    if (col < 256) {
                        store2((float*)C + (size_t)row * 256 + col, v0 * SCALE, v1 * SCALE);
                    } else if (col < 512) {
                        store2(kout + (size_t)row * 256 + (col - 256), v0, v1);
                    } else {
                        store2(vout + (size_t)row * 256 + (col - 512), v0, v1);
                    }
                } else {
                    store2(C + (size_t)row * N + col, v0, v1);
                }
            }
        }
    }
}

// ---------------- dilated neighborhood attention: quad-token sharing --------
// (R12 version — instruction-throughput optimal: full unroll, 4 queries live)
__global__ void __launch_bounds__(256)
attn_kernel(const float* __restrict__ q, const __nv_bfloat16* __restrict__ k,
            const __nv_bfloat16* __restrict__ v, const float* __restrict__ rpb,
            __nv_bfloat16* __restrict__ ctx)
{
    __shared__ float sc[HEADS][4][64];

    const int head = threadIdx.y;
    const int lane = threadIdx.x;
    const int gg = lane >> 2, e = lane & 3;

    const int b   = blockIdx.x;
    const int bi  = b & 15, bj = (b >> 4) & 15, par = b >> 8;
    const int ri  = par & 1, rj = par >> 1;
    const int gi0 = bi * 2, gj0 = bj * 2;

    int si0 = gi0 - 3; si0 = si0 < 0 ? 0 : (si0 > 25 ? 25 : si0);
    int si1 = gi0 - 2; si1 = si1 < 0 ? 0 : (si1 > 25 ? 25 : si1);
    int sj0 = gj0 - 3; sj0 = sj0 < 0 ? 0 : (sj0 > 25 ? 25 : sj0);
    int sj1 = gj0 - 2; sj1 = sj1 < 0 ? 0 : (sj1 > 25 ? 25 : sj1);
    const int dr1 = si1 - si0, dc1 = sj1 - sj0;

    int sjg = sj0 + gg; sjg = sjg > 31 ? 31 : sjg;
    const int kj = sjg * 2 + rj;
    const int choff = head * HD + e * 8;
    const int kcoff = kj * CC + choff;

    float2 qv[4][4];
    int toks[4];
    #pragma unroll
    for (int a = 0; a < 2; a++) {
        #pragma unroll
        for (int c = 0; c < 2; c++) {
            int tok = (2*(gi0 + a) + ri) * WW + 2*(gj0 + c) + rj;
            int qq_ = a*2 + c;
            toks[qq_] = tok;
            const float* qp = q + (size_t)tok * CC + choff;
            float4 qa = ld4(qp), qb = ld4(qp + 4);
            qv[qq_][0] = make_float2(qa.x, qa.y);
            qv[qq_][1] = make_float2(qa.z, qa.w);
            qv[qq_][2] = make_float2(qb.x, qb.y);
            qv[qq_][3] = make_float2(qb.z, qb.w);
        }
    }

    #pragma unroll
    for (int t = 0; t < 8; t++) {
        int sit = si0 + t; sit = sit > 31 ? 31 : sit;
        const int ki = sit * 2 + ri;
        uint4 u = *reinterpret_cast<const uint4*>(k + ki * (WW*CC) + kcoff);
        float2 k0 = bf2f(u.x), k1 = bf2f(u.y), k2 = bf2f(u.z), k3 = bf2f(u.w);
        #pragma unroll
        for (int qq_ = 0; qq_ < 4; qq_++) {
            float2 p2 = fmul2(qv[qq_][0], k0);
            p2 = ffma2(qv[qq_][1], k1, p2);
            p2 = ffma2(qv[qq_][2], k2, p2);
            p2 = ffma2(qv[qq_][3], k3, p2);
            float pt = p2.x + p2.y;
            pt += __shfl_xor_sync(0xffffffffu, pt, 1);
            pt += __shfl_xor_sync(0xffffffffu, pt, 2);
            if (e == 0) sc[head][qq_][t*8 + gg] = pt;
        }
    }
    __syncwarp();

    const float* br = rpb + head * 169;
    float inv[4];
    #pragma unroll
    for (int qq_ = 0; qq_ < 4; qq_++) {
        const int a = qq_ >> 1, c = qq_ & 1;
        const int dra = a ? dr1 : 0, dcc = c ? dc1 : 0;
        const int Bq = (si0 - gi0 - a + 6) * 13 + (sj0 - gj0 - c + 6);
        float s1, s2;
        {
            int p = lane, pr = p >> 3, pc = p & 7;
            bool val = (pr >= dra) && (pr < dra + 7) && (pc >= dcc) && (pc < dcc + 7);
            s1 = val ? sc[head][qq_][p] + br[Bq + pr*13 + pc] : -1e30f;
        }
        {
            int p = lane + 32, pr = p >> 3, pc = p & 7;
            bool val = (pr >= dra) && (pr < dra + 7) && (pc >= dcc) && (pc < dcc + 7);
            s2 = val ? sc[head][qq_][p] + br[Bq + pr*13 + pc] : -1e30f;
        }
        float m = fmaxf(s1, s2);
        #pragma unroll
        for (int o = 16; o; o >>= 1) m = fmaxf(m, __shfl_xor_sync(0xffffffffu, m, o));
        float e1 = __expf(s1 - m), e2 = __expf(s2 - m);
        float ss = e1 + e2;
        #pragma unroll
        for (int o = 16; o; o >>= 1) ss += __shfl_xor_sync(0xffffffffu, ss, o);
        sc[head][qq_][lane]      = e1;
        sc[head][qq_][lane + 32] = e2;
        inv[qq_] = 1.0f / ss;
    }
    __syncwarp();

    float2 acc[4][4];
    #pragma unroll
    for (int qq_ = 0; qq_ < 4; qq_++)
        #pragma unroll
        for (int i = 0; i < 4; i++) acc[qq_][i] = make_float2(0.f, 0.f);

    #pragma unroll
    for (int t = 0; t < 8; t++) {
        int sit = si0 + t; sit = sit > 31 ? 31 : sit;
        const int ki = sit * 2 + ri;
        uint4 u = *reinterpret_cast<const uint4*>(v + ki * (WW*CC) + kcoff);
        float2 v0 = bf2f(u.x), v1 = bf2f(u.y), v2 = bf2f(u.z), v3 = bf2f(u.w);
        #pragma unroll
        for (int qq_ = 0; qq_ < 4; qq_++) {
            float w = sc[head][qq_][t*8 + gg];
            float2 w2 = make_float2(w, w);
            acc[qq_][0] = ffma2(w2, v0, acc[qq_][0]);
            acc[qq_][1] = ffma2(w2, v1, acc[qq_][1]);
            acc[qq_][2] = ffma2(w2, v2, acc[qq_][2]);
            acc[qq_][3] = ffma2(w2, v3, acc[qq_][3]);
        }
    }

    #pragma unroll
    for (int o = 4; o <= 16; o <<= 1) {
        #pragma unroll
        for (int qq_ = 0; qq_ < 4; qq_++) {
            #pragma unroll
            for (int i = 0; i < 4; i++) {
                acc[qq_][i].x += __shfl_xor_sync(0xffffffffu, acc[qq_][i].x, o);
                acc[qq_][i].y += __shfl_xor_sync(0xffffffffu, acc[qq_][i].y, o);
            }
        }
    }
    if (gg == 0) {
        #pragma unroll
        for (int qq_ = 0; qq_ < 4; qq_++) {
            float iv = inv[qq_];
            __nv_bfloat162 o0 = __floats2bfloat162_rn(acc[qq_][0].x*iv, acc[qq_][0].y*iv);
            __nv_bfloat162 o1 = __floats2bfloat162_rn(acc[qq_][1].x*iv, acc[qq_][1].y*iv);
            __nv_bfloat162 o2 = __floats2bfloat162_rn(acc[qq_][2].x*iv, acc[qq_][2].y*iv);
            __nv_bfloat162 o3 = __floats2bfloat162_rn(acc[qq_][3].x*iv, acc[qq_][3].y*iv);
            uint4 pk = make_uint4(*reinterpret_cast<uint32_t*>(&o0),
                                  *reinterpret_cast<uint32_t*>(&o1),
                                  *reinterpret_cast<uint32_t*>(&o2),
                                  *reinterpret_cast<uint32_t*>(&o3));
            *reinterpret_cast<uint4*>(ctx + (size_t)toks[qq_]*CC + choff) = pk;
        }
    }
}

// ---------------- launch ----------------
extern "C" void kernel_launch(void* const* d_in, const int* in_sizes, int n_in,
                              void* d_out, int out_size)
{
    const float* x     = (const float*)d_in[0];
    const float* ln1_g = (const float*)d_in[1];
    const float* ln1_b = (const float*)d_in[2];
    const float* wq    = (const float*)d_in[3];
    const float* bq    = (const float*)d_in[4];
    const float* wk    = (const float*)d_in[5];
    const float* bk    = (const float*)d_in[6];
    const float* wv    = (const float*)d_in[7];
    const float* bv    = (const float*)d_in[8];
    const float* rpb   = (const float*)d_in[9];
    const float* wo    = (const float*)d_in[10];
    const float* bo    = (const float*)d_in[11];
    const float* ln2_g = (const float*)d_in[12];
    const float* ln2_b = (const float*)d_in[13];
    const float* w1    = (const float*)d_in[14];
    const float* b1    = (const float*)d_in[15];
    const float* w2    = (const float*)d_in[16];
    const float* b2    = (const float*)d_in[17];
    float* out = (float*)d_out;

    __nv_bfloat16 *hs, *kq, *vq, *ctxp, *y, *t;
    __nv_bfloat16 *wqkv_b, *wo_b, *w1_b, *w2_b;
    float *qq, *hs2, *bqkv;
    cudaGetSymbolAddress((void**)&hs,     g_hs);
    cudaGetSymbolAddress((void**)&qq,     g_q);
    cudaGetSymbolAddress((void**)&kq,     g_k);
    cudaGetSymbolAddress((void**)&vq,     g_v);
    cudaGetSymbolAddress((void**)&ctxp,   g_ctx);
    cudaGetSymbolAddress((void**)&hs2,    g_hs2);
    cudaGetSymbolAddress((void**)&y,      g_y);
    cudaGetSymbolAddress((void**)&t,      g_t);
    cudaGetSymbolAddress((void**)&wqkv_b, g_wqkv_b);
    cudaGetSymbolAddress((void**)&wo_b,   g_wo_b);
    cudaGetSymbolAddress((void**)&w1_b,   g_w1_b);
    cudaGetSymbolAddress((void**)&w2_b,   g_w2_b);
    cudaGetSymbolAddress((void**)&bqkv,   g_bqkv);

    // 1) fused LN1 + weight pack (independent work, one launch)
    ln1_pack_kernel<<<1280, 256>>>(x, ln1_g, ln1_b, hs,
                                   wq, wk, wv, wo, w1, w2, bq, bk, bv);

    // 2) QKV GEMM: [4096,256] @ [256,768] -> q fp32(scaled) | k bf16 | v bf16
    {
        dim3 grid(768/64, NTOK/64);
        bgemm_kernel<3, float><<<grid, 256>>>(hs, wqkv_b, bqkv, nullptr, qq,
                                              kq, vq, NTOK, 768, CC);
    }

    // 3) attention -> bf16 ctx (quad-token blocks)
    {
        dim3 blk(32, HEADS);
        attn_kernel<<<1024, blk>>>(qq, kq, vq, rpb, ctxp);
    }

    // 4) wo GEMM + residual(x): hs2 = ctx@wo + bo + x  (fp32)
    {
        dim3 grid(CC/64, NTOK/64);
        bgemm_kernel<2, float><<<grid, 256>>>(ctxp, wo_b, bo, x, hs2,
                                              nullptr, nullptr, NTOK, CC, CC);
    }

    // 5) LN2 -> bf16
    ln_kernel<<<NTOK/8, 256>>>(hs2, ln2_g, ln2_b, y);

    // 6) w1 GEMM + exact GELU -> bf16 t
    {
        dim3 grid(FF/64, NTOK/64);
        bgemm_kernel<1, __nv_bfloat16><<<grid, 256>>>(y, w1_b, b1, nullptr, t,
                                                      nullptr, nullptr, NTOK, FF, CC);
    }

    // 7) w2 GEMM + residual(hs2): out = t@w2 + b2 + hs2  (fp32)
    {
        dim3 grid(CC/64, NTOK/64);
        bgemm_kernel<2, float><<<grid, 256>>>(t, w2_b, b2, hs2, out,
                                              nullptr, nullptr, NTOK, CC, FF);
    }
}

// round 16
// speedup vs baseline: 1.1160x; 1.0004x over previous
#include <cuda_runtime.h>
#include <cuda_bf16.h>
#include <math.h>
#include <stdint.h>

// Problem constants
#define BB 1
#define HH 64
#define WW 64
#define CC 256
#define HEADS 8
#define HD 32
#define KK 7
#define DIL 2
#define FF 1024
#define NTOK (HH*WW)            // 4096
#define SCALE 0.17677669529663687f  // 1/sqrt(32)

// ---------------- scratch (device globals; no runtime alloc) ----------------
__device__ __nv_bfloat16 g_hs [NTOK*CC];     // LN1(x), bf16 (GEMM A)
__device__ float         g_q  [NTOK*CC];     // q fp32, pre-scaled
__device__ __nv_bfloat16 g_k  [NTOK*CC];     // k bf16
__device__ __nv_bfloat16 g_v  [NTOK*CC];     // v bf16
__device__ __nv_bfloat16 g_ctx[NTOK*CC];     // attention context, bf16
__device__ float         g_hs2[NTOK*CC];     // x + attn_out, fp32
__device__ __nv_bfloat16 g_y  [NTOK*CC];     // LN2(hs2), bf16
__device__ __nv_bfloat16 g_t  [NTOK*FF];     // gelu(y@w1+b1), bf16
// bf16 weights, plain [k][n] layout
__device__ __nv_bfloat16 g_wqkv_b[256*768];
__device__ __nv_bfloat16 g_wo_b  [256*256];
__device__ __nv_bfloat16 g_w1_b  [256*1024];
__device__ __nv_bfloat16 g_w2_b  [1024*256];
__device__ float         g_bqkv  [768];

__device__ __forceinline__ float4 ld4(const float* p) {
    return *reinterpret_cast<const float4*>(p);
}
__device__ __forceinline__ float2 bf2f(uint32_t u) {
    __nv_bfloat162 h = *reinterpret_cast<__nv_bfloat162*>(&u);
    return __bfloat1622float2(h);
}
__device__ __forceinline__ float2 ffma2(float2 a, float2 b, float2 c) {
    float2 d;
    asm("fma.rn.f32x2 %0, %1, %2, %3;"
        : "=l"(*reinterpret_cast<uint64_t*>(&d))
        : "l"(*reinterpret_cast<const uint64_t*>(&a)),
          "l"(*reinterpret_cast<const uint64_t*>(&b)),
          "l"(*reinterpret_cast<const uint64_t*>(&c)));
    return d;
}
__device__ __forceinline__ float2 fmul2(float2 a, float2 b) {
    float2 d;
    asm("mul.rn.f32x2 %0, %1, %2;"
        : "=l"(*reinterpret_cast<uint64_t*>(&d))
        : "l"(*reinterpret_cast<const uint64_t*>(&a)),
          "l"(*reinterpret_cast<const uint64_t*>(&b)));
    return d;
}
__device__ __forceinline__ uint32_t smem_u32(const void* p) {
    uint32_t a;
    asm("{ .reg .u64 t; cvta.to.shared.u64 t, %1; cvt.u32.u64 %0, t; }"
        : "=r"(a) : "l"(p));
    return a;
}
__device__ __forceinline__ void ldsm_x4(uint32_t (&r)[4], uint32_t addr) {
    asm volatile("ldmatrix.sync.aligned.m8n8.x4.shared.b16 {%0,%1,%2,%3}, [%4];"
        : "=r"(r[0]), "=r"(r[1]), "=r"(r[2]), "=r"(r[3]) : "r"(addr));
}
__device__ __forceinline__ void ldsm_x4_t(uint32_t (&r)[4], uint32_t addr) {
    asm volatile("ldmatrix.sync.aligned.m8n8.x4.trans.shared.b16 {%0,%1,%2,%3}, [%4];"
        : "=r"(r[0]), "=r"(r[1]), "=r"(r[2]), "=r"(r[3]) : "r"(addr));
}
__device__ __forceinline__ void mma_bf16(float (&d)[4], const uint32_t (&a)[4],
                                         const uint32_t (&b)[2]) {
    asm volatile(
        "mma.sync.aligned.m16n8k16.row.col.f32.bf16.bf16.f32 "
        "{%0,%1,%2,%3}, {%4,%5,%6,%7}, {%8,%9}, {%0,%1,%2,%3};\n"
        : "+f"(d[0]), "+f"(d[1]), "+f"(d[2]), "+f"(d[3])
        : "r"(a[0]), "r"(a[1]), "r"(a[2]), "r"(a[3]),
          "r"(b[0]), "r"(b[1]));
}
__device__ __forceinline__ void cpa16(uint32_t dst, const void* src) {
    asm volatile("cp.async.cg.shared.global [%0], [%1], 16;"
        :: "r"(dst), "l"(src) : "memory");
}
#define CP_COMMIT() asm volatile("cp.async.commit_group;" ::: "memory")
#define CP_WAIT(n)  asm volatile("cp.async.wait_group %0;" :: "n"(n) : "memory")

__device__ __forceinline__ uint2 f4_to_bf4(float4 v) {
    __nv_bfloat162 h0 = __floats2bfloat162_rn(v.x, v.y);
    __nv_bfloat162 h1 = __floats2bfloat162_rn(v.z, v.w);
    return make_uint2(*reinterpret_cast<uint32_t*>(&h0),
                      *reinterpret_cast<uint32_t*>(&h1));
}

// ---------------- LN row helper (one warp per row) ----------------
__device__ __forceinline__ void ln_row(const float* __restrict__ x,
                                       const float* __restrict__ g,
                                       const float* __restrict__ b,
                                       __nv_bfloat16* __restrict__ out,
                                       int row, int lane)
{
    const float* xr = x + (size_t)row * CC + lane * 8;
    float4 v0 = ld4(xr), v1 = ld4(xr + 4);
    float s  = v0.x + v0.y + v0.z + v0.w + v1.x + v1.y + v1.z + v1.w;
    float sq = v0.x*v0.x + v0.y*v0.y + v0.z*v0.z + v0.w*v0.w
             + v1.x*v1.x + v1.y*v1.y + v1.z*v1.z + v1.w*v1.w;
    #pragma unroll
    for (int o = 16; o; o >>= 1) {
        s  += __shfl_xor_sync(0xffffffffu, s,  o);
        sq += __shfl_xor_sync(0xffffffffu, sq, o);
    }
    float mean = s * (1.0f/CC);
    float var  = sq * (1.0f/CC) - mean*mean;
    float inv  = rsqrtf(var + 1e-5f);
    float4 g0 = ld4(g + lane*8), g1 = ld4(g + lane*8 + 4);
    float4 b0 = ld4(b + lane*8), b1 = ld4(b + lane*8 + 4);
    __nv_bfloat162 o0 = __floats2bfloat162_rn((v0.x-mean)*inv*g0.x + b0.x,
                                              (v0.y-mean)*inv*g0.y + b0.y);
    __nv_bfloat162 o1 = __floats2bfloat162_rn((v0.z-mean)*inv*g0.z + b0.z,
                                              (v0.w-mean)*inv*g0.w + b0.w);
    __nv_bfloat162 o2 = __floats2bfloat162_rn((v1.x-mean)*inv*g1.x + b1.x,
                                              (v1.y-mean)*inv*g1.y + b1.y);
    __nv_bfloat162 o3 = __floats2bfloat162_rn((v1.z-mean)*inv*g1.z + b1.z,
                                              (v1.w-mean)*inv*g1.w + b1.w);
    uint4 pk = make_uint4(*reinterpret_cast<uint32_t*>(&o0),
                          *reinterpret_cast<uint32_t*>(&o1),
                          *reinterpret_cast<uint32_t*>(&o2),
                          *reinterpret_cast<uint32_t*>(&o3));
    *reinterpret_cast<uint4*>(out + (size_t)row * CC + lane * 8) = pk;
}

// ---------------- fused LN1 + weight pack (independent work, one launch) ----
__global__ void ln1_pack_kernel(const float* __restrict__ x,
                                const float* __restrict__ ln1_g, const float* __restrict__ ln1_b,
                                __nv_bfloat16* __restrict__ hs,
                                const float* __restrict__ wq, const float* __restrict__ wk,
                                const float* __restrict__ wv, const float* __restrict__ wo,
                                const float* __restrict__ w1, const float* __restrict__ w2,
                                const float* __restrict__ bq, const float* __restrict__ bk,
                                const float* __restrict__ bv)
{
    if (blockIdx.x < 512) {
        int row = blockIdx.x * 8 + (threadIdx.x >> 5);
        ln_row(x, ln1_g, ln1_b, hs, row, threadIdx.x & 31);
        return;
    }
    int i4 = (blockIdx.x - 512) * 256 + threadIdx.x;   // vector (4-elem) index
    if (i4 < 49152) {                            // wqkv: 256x768
        int idx = i4 * 4;
        int k = idx / 768, n = idx % 768;
        const float* W; int nn;
        if      (n < 256) { W = wq; nn = n; }
        else if (n < 512) { W = wk; nn = n - 256; }
        else              { W = wv; nn = n - 512; }
        float4 v = ld4(W + (size_t)k * 256 + nn);
        *reinterpret_cast<uint2*>(g_wqkv_b + idx) = f4_to_bf4(v);
    } else if (i4 < 65536) {                     // wo
        int t = (i4 - 49152) * 4;
        *reinterpret_cast<uint2*>(g_wo_b + t) = f4_to_bf4(ld4(wo + t));
    } else if (i4 < 131072) {                    // w1
        int t = (i4 - 65536) * 4;
        *reinterpret_cast<uint2*>(g_w1_b + t) = f4_to_bf4(ld4(w1 + t));
    } else if (i4 < 196608) {                    // w2
        int t = (i4 - 131072) * 4;
        *reinterpret_cast<uint2*>(g_w2_b + t) = f4_to_bf4(ld4(w2 + t));
    }
    if (i4 < 768) {
        float v;
        if      (i4 < 256) v = bq[i4];
        else if (i4 < 512) v = bk[i4 - 256];
        else               v = bv[i4 - 512];
        g_bqkv[i4] = v;
    }
}

// ---------------- LayerNorm standalone (LN2) ----------------
__global__ void ln_kernel(const float* __restrict__ x, const float* __restrict__ g,
                          const float* __restrict__ b, __nv_bfloat16* __restrict__ out)
{
    ln_row(x, g, b, out, blockIdx.x * 8 + (threadIdx.x >> 5), threadIdx.x & 31);
}

// ---------------- bf16 tensor-core GEMM: cp.async 3-stage pipeline ----------
// BM64 tiles: 2Mx4N warps, warp 32x16 (2x2 frags), minctas=3. (R12 config)
// EPI 1: gelu(+bias) ; EPI 2: +bias + res ; EPI 3: qkv split
#define A_STR 20   // uint32 per A row (80B)
#define B_STR 36   // uint32 per B row (144B)
#define NSTG 3
#define BMT 64

__device__ __forceinline__ void store2(float* p, float v0, float v1) {
    *reinterpret_cast<float2*>(p) = make_float2(v0, v1);
}
__device__ __forceinline__ void store2(__nv_bfloat16* p, float v0, float v1) {
    *reinterpret_cast<__nv_bfloat162*>(p) = __floats2bfloat162_rn(v0, v1);
}

template<int EPI, typename OutT>
__global__ void __launch_bounds__(256, 3)
bgemm_kernel(const __nv_bfloat16* __restrict__ A, const __nv_bfloat16* __restrict__ W,
             const float* __restrict__ bias, const float* __restrict__ res,
             OutT* __restrict__ C, __nv_bfloat16* __restrict__ kout,
             __nv_bfloat16* __restrict__ vout, int M, int N, int K)
{
    constexpr int WM = 2, WN = 4, NF = 2;
    constexpr uint32_t A_STG = BMT * A_STR * 4;
    constexpr uint32_t B_STG = 32 * B_STR * 4;

    __shared__ __align__(16) uint32_t As[NSTG][BMT * A_STR];
    __shared__ __align__(16) uint32_t Bs[NSTG][32 * B_STR];

    const int tid  = threadIdx.x;
    const int lane = tid & 31, warp = tid >> 5;
    const int wm = warp % WM, wn = warp / WM;
    const int g = lane >> 2, c = lane & 3;
    const int bm = blockIdx.y * BMT, bn = blockIdx.x * 64;

    const int arow = (tid >> 1) & 63, ahalf = (tid & 1);
    const bool aload = (tid < 128);
    const int bkrow = tid >> 3, bnch = (tid & 7) * 8;
    const __nv_bfloat16* Ag = A + (size_t)(bm + arow) * K + ahalf * 16;
    const __nv_bfloat16* Wg = W + (size_t)bkrow * N + bn + bnch;

    const uint32_t aBase = smem_u32(As);
    const uint32_t bBase = smem_u32(Bs);
    const uint32_t asto = (uint32_t)(arow * A_STR + ahalf * 8) * 4;
    const uint32_t bsto = (uint32_t)(bkrow * B_STR + (tid & 7) * 4) * 4;

    const uint32_t aoff = (uint32_t)(wm*32 + (lane & 15)) * 80 + (lane >> 4) * 16;
    const uint32_t boff = (uint32_t)(lane & 15) * 144 +
                          (uint32_t)(wn*(NF*8) + (lane >> 4)*8) * 2;

    float acc[2][NF][4];
    #pragma unroll
    for (int mf = 0; mf < 2; mf++)
        #pragma unroll
        for (int nf = 0; nf < NF; nf++)
            #pragma unroll
            for (int e = 0; e < 4; e++) acc[mf][nf][e] = 0.f;

    const int NT = K / 32;

    auto issue = [&](int kt, int s) {
        if (aload) {
            const __nv_bfloat16* ag = Ag + kt * 32;
            uint32_t d = aBase + (uint32_t)s * A_STG + asto;
            cpa16(d, ag);
            cpa16(d + 16, ag + 8);
        }
        cpa16(bBase + (uint32_t)s * B_STG + bsto, Wg + (size_t)kt * 32 * N);
        CP_COMMIT();
    };

    issue(0, 0);
    issue(1, 1);

    for (int kt = 0; kt < NT; kt++) {
        CP_WAIT(NSTG - 2);
        __syncthreads();
        const int s = kt % NSTG;
        if (kt + NSTG - 1 < NT) {
            issue(kt + NSTG - 1, (kt + NSTG - 1) % NSTG);
        } else {
            CP_COMMIT();   // empty group keeps wait_group invariant at the tail
        }

        const uint32_t ab = aBase + (uint32_t)s * A_STG;
        const uint32_t bb = bBase + (uint32_t)s * B_STG;
        #pragma unroll
        for (int ks = 0; ks < 32; ks += 16) {
            uint32_t af[2][4], bf[NF][2];
            #pragma unroll
            for (int mf = 0; mf < 2; mf++)
                ldsm_x4(af[mf], ab + aoff + (uint32_t)(mf * 16 * 80 + ks * 2));
            {
                uint32_t br[4];
                ldsm_x4_t(br, bb + boff + (uint32_t)(ks * 144));
                bf[0][0] = br[0]; bf[0][1] = br[1];
                bf[1][0] = br[2]; bf[1][1] = br[3];
            }
            #pragma unroll
            for (int mf = 0; mf < 2; mf++)
                #pragma unroll
                for (int nf = 0; nf < NF; nf++)
                    mma_bf16(acc[mf][nf], af[mf], bf[nf]);
        }
    }
    __syncthreads();

    #pragma unroll
    for (int mf = 0; mf < 2; mf++) {
        #pragma unroll
        for (int nf = 0; nf < NF; nf++) {
            int row0 = bm + wm * 32 + mf * 16 + g;
            int col  = bn + wn * (NF*8) + nf * 8 + c * 2;
            float bx = bias[col], by = bias[col + 1];
            #pragma unroll
            for (int h = 0; h < 2; h++) {
                int row = row0 + h * 8;
                float v0 = acc[mf][nf][h * 2 + 0] + bx;
                float v1 = acc[mf][nf][h * 2 + 1] + by;
                if (EPI == 1) {
                    v0 *= normcdff(v0);
                    v1 *= normcdff(v1);
                } else if (EPI == 2) {
                    float2 r = *reinterpret_cast<const float2*>(res + (size_t)row * N + col);
                    v0 += r.x; v1 += r.y;
                }
                if (EPI == 3) {
                    if (col < 256) {
                        store2((float*)C + (size_t)row * 256 + col, v0 * SCALE, v1 * SCALE);
                    } else if (col < 512) {
                        store2(kout + (size_t)row * 256 + (col - 256), v0, v1);
                    } else {
                        store2(vout + (size_t)row * 256 + (col - 512), v0, v1);
                    }
                } else {
                    store2(C + (size_t)row * N + col, v0, v1);
                }
            }
        }
    }
}

// ---------------- dilated neighborhood attention: quad-token sharing --------
// R12 schedule, register-capped to 84 (3 blocks/SM); toks recomputed at
// output time instead of being kept live across the whole kernel.
__global__ void __launch_bounds__(256, 3)
attn_kernel(const float* __restrict__ q, const __nv_bfloat16* __restrict__ k,
            const __nv_bfloat16* __restrict__ v, const float* __restrict__ rpb,
            __nv_bfloat16* __restrict__ ctx)
{
    __shared__ float sc[HEADS][4][64];

    const int head = threadIdx.y;
    const int lane = threadIdx.x;
    const int gg = lane >> 2, e = lane & 3;

    const int b   = blockIdx.x;
    const int bi  = b & 15, bj = (b >> 4) & 15, par = b >> 8;
    const int ri  = par & 1, rj = par >> 1;
    const int gi0 = bi * 2, gj0 = bj * 2;

    int si0 = gi0 - 3; si0 = si0 < 0 ? 0 : (si0 > 25 ? 25 : si0);
    int si1 = gi0 - 2; si1 = si1 < 0 ? 0 : (si1 > 25 ? 25 : si1);
    int sj0 = gj0 - 3; sj0 = sj0 < 0 ? 0 : (sj0 > 25 ? 25 : sj0);
    int sj1 = gj0 - 2; sj1 = sj1 < 0 ? 0 : (sj1 > 25 ? 25 : sj1);
    const int dr1 = si1 - si0, dc1 = sj1 - sj0;

    int sjg = sj0 + gg; sjg = sjg > 31 ? 31 : sjg;
    const int kj = sjg * 2 + rj;
    const int choff = head * HD + e * 8;
    const int kcoff = kj * CC + choff;

    float2 qv[4][4];
    #pragma unroll
    for (int a = 0; a < 2; a++) {
        #pragma unroll
        for (int c = 0; c < 2; c++) {
            int tok = (2*(gi0 + a) + ri) * WW + 2*(gj0 + c) + rj;
            int qq_ = a*2 + c;
            const float* qp = q + (size_t)tok * CC + choff;
            float4 qa = ld4(qp), qb = ld4(qp + 4);
            qv[qq_][0] = make_float2(qa.x, qa.y);
            qv[qq_][1] = make_float2(qa.z, qa.w);
            qv[qq_][2] = make_float2(qb.x, qb.y);
            qv[qq_][3] = make_float2(qb.z, qb.w);
        }
    }

    #pragma unroll
    for (int t = 0; t < 8; t++) {
        int sit = si0 + t; sit = sit > 31 ? 31 : sit;
        const int ki = sit * 2 + ri;
        uint4 u = *reinterpret_cast<const uint4*>(k + ki * (WW*CC) + kcoff);
        float2 k0 = bf2f(u.x), k1 = bf2f(u.y), k2 = bf2f(u.z), k3 = bf2f(u.w);
        #pragma unroll
        for (int qq_ = 0; qq_ < 4; qq_++) {
            float2 p2 = fmul2(qv[qq_][0], k0);
            p2 = ffma2(qv[qq_][1], k1, p2);
            p2 = ffma2(qv[qq_][2], k2, p2);
            p2 = ffma2(qv[qq_][3], k3, p2);
            float pt = p2.x + p2.y;
            pt += __shfl_xor_sync(0xffffffffu, pt, 1);
            pt += __shfl_xor_sync(0xffffffffu, pt, 2);
            if (e == 0) sc[head][qq_][t*8 + gg] = pt;
        }
    }
    __syncwarp();

    const float* br = rpb + head * 169;
    float inv[4];
    #pragma unroll
    for (int qq_ = 0; qq_ < 4; qq_++) {
        const int a = qq_ >> 1, c = qq_ & 1;
        const int dra = a ? dr1 : 0, dcc = c ? dc1 : 0;
        const int Bq = (si0 - gi0 - a + 6) * 13 + (sj0 - gj0 - c + 6);
        float s1, s2;
        {
            int p = lane, pr = p >> 3, pc = p & 7;
            bool val = (pr >= dra) && (pr < dra + 7) && (pc >= dcc) && (pc < dcc + 7);
            s1 = val ? sc[head][qq_][p] + br[Bq + pr*13 + pc] : -1e30f;
        }
        {
            int p = lane + 32, pr = p >> 3, pc = p & 7;
            bool val = (pr >= dra) && (pr < dra + 7) && (pc >= dcc) && (pc < dcc + 7);
            s2 = val ? sc[head][qq_][p] + br[Bq + pr*13 + pc] : -1e30f;
        }
        float m = fmaxf(s1, s2);
        #pragma unroll
        for (int o = 16; o; o >>= 1) m = fmaxf(m, __shfl_xor_sync(0xffffffffu, m, o));
        float e1 = __expf(s1 - m), e2 = __expf(s2 - m);
        float ss = e1 + e2;
        #pragma unroll
        for (int o = 16; o; o >>= 1) ss += __shfl_xor_sync(0xffffffffu, ss, o);
        sc[head][qq_][lane]      = e1;
        sc[head][qq_][lane + 32] = e2;
        inv[qq_] = 1.0f / ss;
    }
    __syncwarp();

    float2 acc[4][4];
    #pragma unroll
    for (int qq_ = 0; qq_ < 4; qq_++)
        #pragma unroll
        for (int i = 0; i < 4; i++) acc[qq_][i] = make_float2(0.f, 0.f);

    #pragma unroll
    for (int t = 0; t < 8; t++) {
        int sit = si0 + t; sit = sit > 31 ? 31 : sit;
        const int ki = sit * 2 + ri;
        uint4 u = *reinterpret_cast<const uint4*>(v + ki * (WW*CC) + kcoff);
        float2 v0 = bf2f(u.x), v1 = bf2f(u.y), v2 = bf2f(u.z), v3 = bf2f(u.w);
        #pragma unroll
        for (int qq_ = 0; qq_ < 4; qq_++) {
            float w = sc[head][qq_][t*8 + gg];
            float2 w2 = make_float2(w, w);
            acc[qq_][0] = ffma2(w2, v0, acc[qq_][0]);
            acc[qq_][1] = ffma2(w2, v1, acc[qq_][1]);
            acc[qq_][2] = ffma2(w2, v2, acc[qq_][2]);
            acc[qq_][3] = ffma2(w2, v3, acc[qq_][3]);
        }
    }

    #pragma unroll
    for (int o = 4; o <= 16; o <<= 1) {
        #pragma unroll
        for (int qq_ = 0; qq_ < 4; qq_++) {
            #pragma unroll
            for (int i = 0; i < 4; i++) {
                acc[qq_][i].x += __shfl_xor_sync(0xffffffffu, acc[qq_][i].x, o);
                acc[qq_][i].y += __shfl_xor_sync(0xffffffffu, acc[qq_][i].y, o);
            }
        }
    }
    if (gg == 0) {
        #pragma unroll
        for (int a = 0; a < 2; a++) {
            #pragma unroll
            for (int c = 0; c < 2; c++) {
                int qq_ = a*2 + c;
                int tok = (2*(gi0 + a) + ri) * WW + 2*(gj0 + c) + rj;
                float iv = inv[qq_];
                __nv_bfloat162 o0 = __floats2bfloat162_rn(acc[qq_][0].x*iv, acc[qq_][0].y*iv);
                __nv_bfloat162 o1 = __floats2bfloat162_rn(acc[qq_][1].x*iv, acc[qq_][1].y*iv);
                __nv_bfloat162 o2 = __floats2bfloat162_rn(acc[qq_][2].x*iv, acc[qq_][2].y*iv);
                __nv_bfloat162 o3 = __floats2bfloat162_rn(acc[qq_][3].x*iv, acc[qq_][3].y*iv);
                uint4 pk = make_uint4(*reinterpret_cast<uint32_t*>(&o0),
                                      *reinterpret_cast<uint32_t*>(&o1),
                                      *reinterpret_cast<uint32_t*>(&o2),
                                      *reinterpret_cast<uint32_t*>(&o3));
                *reinterpret_cast<uint4*>(ctx + (size_t)tok*CC + choff) = pk;
            }
        }
    }
}

// ---------------- launch ----------------
extern "C" void kernel_launch(void* const* d_in, const int* in_sizes, int n_in,
                              void* d_out, int out_size)
{
    const float* x     = (const float*)d_in[0];
    const float* ln1_g = (const float*)d_in[1];
    const float* ln1_b = (const float*)d_in[2];
    const float* wq    = (const float*)d_in[3];
    const float* bq    = (const float*)d_in[4];
    const float* wk    = (const float*)d_in[5];
    const float* bk    = (const float*)d_in[6];
    const float* wv    = (const float*)d_in[7];
    const float* bv    = (const float*)d_in[8];
    const float* rpb   = (const float*)d_in[9];
    const float* wo    = (const float*)d_in[10];
    const float* bo    = (const float*)d_in[11];
    const float* ln2_g = (const float*)d_in[12];
    const float* ln2_b = (const float*)d_in[13];
    const float* w1    = (const float*)d_in[14];
    const float* b1    = (const float*)d_in[15];
    const float* w2    = (const float*)d_in[16];
    const float* b2    = (const float*)d_in[17];
    float* out = (float*)d_out;

    __nv_bfloat16 *hs, *kq, *vq, *ctxp, *y, *t;
    __nv_bfloat16 *wqkv_b, *wo_b, *w1_b, *w2_b;
    float *qq, *hs2, *bqkv;
    cudaGetSymbolAddress((void**)&hs,     g_hs);
    cudaGetSymbolAddress((void**)&qq,     g_q);
    cudaGetSymbolAddress((void**)&kq,     g_k);
    cudaGetSymbolAddress((void**)&vq,     g_v);
    cudaGetSymbolAddress((void**)&ctxp,   g_ctx);
    cudaGetSymbolAddress((void**)&hs2,    g_hs2);
    cudaGetSymbolAddress((void**)&y,      g_y);
    cudaGetSymbolAddress((void**)&t,      g_t);
    cudaGetSymbolAddress((void**)&wqkv_b, g_wqkv_b);
    cudaGetSymbolAddress((void**)&wo_b,   g_wo_b);
    cudaGetSymbolAddress((void**)&w1_b,   g_w1_b);
    cudaGetSymbolAddress((void**)&w2_b,   g_w2_b);
    cudaGetSymbolAddress((void**)&bqkv,   g_bqkv);

    // 1) fused LN1 + weight pack (independent work, one launch)
    ln1_pack_kernel<<<1280, 256>>>(x, ln1_g, ln1_b, hs,
                                   wq, wk, wv, wo, w1, w2, bq, bk, bv);

    // 2) QKV GEMM: [4096,256] @ [256,768] -> q fp32(scaled) | k bf16 | v bf16
    {
        dim3 grid(768/64, NTOK/64);
        bgemm_kernel<3, float><<<grid, 256>>>(hs, wqkv_b, bqkv, nullptr, qq,
                                              kq, vq, NTOK, 768, CC);
    }

    // 3) attention -> bf16 ctx (quad-token blocks)
    {
        dim3 blk(32, HEADS);
        attn_kernel<<<1024, blk>>>(qq, kq, vq, rpb, ctxp);
    }

    // 4) wo GEMM + residual(x): hs2 = ctx@wo + bo + x  (fp32)
    {
        dim3 grid(CC/64, NTOK/64);
        bgemm_kernel<2, float><<<grid, 256>>>(ctxp, wo_b, bo, x, hs2,
                                              nullptr, nullptr, NTOK, CC, CC);
    }

    // 5) LN2 -> bf16
    ln_kernel<<<NTOK/8, 256>>>(hs2, ln2_g, ln2_b, y);

    // 6) w1 GEMM + exact GELU -> bf16 t
    {
        dim3 grid(FF/64, NTOK/64);
        bgemm_kernel<1, __nv_bfloat16><<<grid, 256>>>(y, w1_b, b1, nullptr, t,
                                                      nullptr, nullptr, NTOK, FF, CC);
    }

    // 7) w2 GEMM + residual(hs2): out = t@w2 + b2 + hs2  (fp32)
    {
        dim3 grid(CC/64, NTOK/64);
        bgemm_kernel<2, float><<<grid, 256>>>(t, w2_b, b2, hs2, out,
                                              nullptr, nullptr, NTOK, CC, FF);
    }
}